// round 9
// baseline (speedup 1.0000x reference)
#include <cuda_runtime.h>
#include <mma.h>
#include <math.h>

using namespace nvcuda;

#define BATCH 64
#define HW    56
#define SEQ   3136
#define EMB   96
#define HEADS 3
#define EH    32
#define WS    7
#define WS2   49
#define NWIN  64
#define N3E   288

#define SCALE 0.17677669529663687f  // 1/sqrt(32)

// Scratch (device globals)
__device__ float g_QKV[BATCH * SEQ * N3E];   // dense [row][288], col = e*3+ksel
__device__ float g_O[BATCH * SEQ * EMB];

__device__ __forceinline__ void mma_tf32(float& d0, float& d1, float& d2, float& d3,
                                         unsigned a0, unsigned a1, unsigned a2, unsigned a3,
                                         unsigned b0, unsigned b1) {
    asm volatile(
        "mma.sync.aligned.m16n8k8.row.col.f32.tf32.tf32.f32 "
        "{%0,%1,%2,%3}, {%4,%5,%6,%7}, {%8,%9}, {%0,%1,%2,%3};\n"
        : "+f"(d0), "+f"(d1), "+f"(d2), "+f"(d3)
        : "r"(a0), "r"(a1), "r"(a2), "r"(a3), "r"(b0), "r"(b1));
}

// ---------------------------------------------------------------------------
// K1: qkv = x @ w1^T + b1 via mma.sync tf32. DENSE output [row][288],
// register-direct float2 stores (no scatter; windowing moved to K2's gather).
// Block tile 128(M) x 96(N) (blockIdx.y = 96-col slice). 256 thr = 8 warps.
// ---------------------------------------------------------------------------
__global__ __launch_bounds__(256) void k_qkv(const float* __restrict__ x,
                                             const float* __restrict__ w1,
                                             const float* __restrict__ b1) {
    __shared__ float As[6144];
    __shared__ float Bs[4608];

    const int M0 = blockIdx.x * 128;
    const int c0 = blockIdx.y * 96;
    const int t = threadIdx.x;
    const int lane = t & 31;
    const int w = t >> 5;
    const int mw = w >> 1;
    const int nw = w & 1;
    const int gID = lane >> 2;
    const int tig = lane & 3;

    const int rA = t >> 1, halfA = t & 1;
    const int gA = rA >> 4, rrA = rA & 15;
    const int fbaseA = gA * 768 + (rrA & 7) * 16 + (rrA >> 3);
    const int ks0A = halfA * 3;
    const int nB = t >> 1, halfB = t & 1;
    const int fbaseB = (nB >> 3) * 64 + (nB & 7) * 8;
    const int ks0B = halfB * 3;

    float d[2][6][4];
    #pragma unroll
    for (int f = 0; f < 2; f++)
        #pragma unroll
        for (int nb = 0; nb < 6; nb++)
            #pragma unroll
            for (int c = 0; c < 4; c++) d[f][nb][c] = 0.f;

    for (int kc = 0; kc < 96; kc += 48) {
        __syncthreads();
        {
            const float* xrow = &x[(M0 + rA) * 96 + kc + halfA * 24];
            #pragma unroll
            for (int j = 0; j < 6; j++) {
                const float4 v = *(const float4*)&xrow[j * 4];
                const int base = fbaseA + (ks0A + (j >> 1)) * 128 + 2 * (j & 1);
                As[base + 0]  = wmma::__float_to_tf32(v.x);
                As[base + 4]  = wmma::__float_to_tf32(v.y);
                As[base + 8]  = wmma::__float_to_tf32(v.z);
                As[base + 12] = wmma::__float_to_tf32(v.w);
            }
        }
        if (t < 192) {
            const float* wrow = &w1[(c0 + nB) * 96 + kc + halfB * 24];
            #pragma unroll
            for (int j = 0; j < 6; j++) {
                const float4 v = *(const float4*)&wrow[j * 4];
                const int base = fbaseB + (ks0B + (j >> 1)) * 768 + (j & 1);
                Bs[base + 0] = wmma::__float_to_tf32(v.x);
                Bs[base + 2] = wmma::__float_to_tf32(v.y);
                Bs[base + 4] = wmma::__float_to_tf32(v.z);
                Bs[base + 6] = wmma::__float_to_tf32(v.w);
            }
        }
        __syncthreads();

        const float4* A4 = (const float4*)As;
        const float2* B2 = (const float2*)Bs;
        #pragma unroll
        for (int ks = 0; ks < 6; ks++) {
            const float4 a0 = A4[((mw * 2 + 0) * 6 + ks) * 32 + lane];
            const float4 a1 = A4[((mw * 2 + 1) * 6 + ks) * 32 + lane];
            float2 bf[6];
            #pragma unroll
            for (int nb = 0; nb < 6; nb++)
                bf[nb] = B2[(ks * 12 + nw * 6 + nb) * 32 + lane];
            #pragma unroll
            for (int nb = 0; nb < 6; nb++) {
                mma_tf32(d[0][nb][0], d[0][nb][1], d[0][nb][2], d[0][nb][3],
                         __float_as_uint(a0.x), __float_as_uint(a0.y),
                         __float_as_uint(a0.z), __float_as_uint(a0.w),
                         __float_as_uint(bf[nb].x), __float_as_uint(bf[nb].y));
                mma_tf32(d[1][nb][0], d[1][nb][1], d[1][nb][2], d[1][nb][3],
                         __float_as_uint(a1.x), __float_as_uint(a1.y),
                         __float_as_uint(a1.z), __float_as_uint(a1.w),
                         __float_as_uint(bf[nb].x), __float_as_uint(bf[nb].y));
            }
        }
    }

    // Dense epilogue: float2 stores straight from registers
    #pragma unroll
    for (int f = 0; f < 2; f++) {
        #pragma unroll
        for (int h = 0; h < 2; h++) {
            const int row = M0 + mw * 32 + f * 16 + gID + 8 * h;
            #pragma unroll
            for (int nb = 0; nb < 6; nb++) {
                const int colp = nw * 48 + nb * 8 + tig * 2;
                float2 o;
                o.x = d[f][nb][h * 2 + 0] + __ldg(&b1[c0 + colp]);
                o.y = d[f][nb][h * 2 + 1] + __ldg(&b1[c0 + colp + 1]);
                *(float2*)&g_QKV[row * N3E + c0 + colp] = o;
            }
        }
    }
}

// ---------------------------------------------------------------------------
// K2: window attention. Gathers Q/K/V from dense g_QKV (roll + window math
// via per-block sRow[] map; Q/K/V adjacent per element). One block per
// (b, head, window), 128 threads. tf32 wmma, smem overlays.
// ---------------------------------------------------------------------------
__global__ __launch_bounds__(128) void k_attn() {
    __shared__ float sm[6912];
    __shared__ int sRow[WS2];
    float (*Qs)[36] = (float(*)[36])sm;
    float (*Ks)[36] = (float(*)[36])(sm + 2304);
    float (*Vs)[36] = (float(*)[36])(sm + 4608);
    float (*Ss)[68] = (float(*)[68])sm;
    float (*Os)[36] = (float(*)[36])sm;

    const int blk = blockIdx.x;
    const int win = blk & 63;
    const int head = (blk >> 6) % 3;
    const int b = blk / (NWIN * HEADS);
    const int t = threadIdx.x;
    const int w = t >> 5, lane = t & 31;
    const int m0 = w * 16;
    const int wh = win >> 3, ww = win & 7;

    // Per-window token map: rolled (yr,xr) -> orig s; base addr incl. head
    if (t < WS2) {
        const int m1 = t / 7, m2 = t % 7;
        const int y  = (wh * WS + m1 + 4) % HW;
        const int xx = (ww * WS + m2 + 4) % HW;
        sRow[t] = (b * SEQ + y * HW + xx) * N3E + head * 96;
    }
    __syncthreads();

    // Stage Q(*scale)/K/V from dense layout (Q,K,V adjacent: +0,+1,+2)
    for (int i = t; i < 64 * EH; i += 128) {
        const int m = i >> 5, k = i & 31;
        float q = 0.f, kk = 0.f, vv = 0.f;
        if (m < WS2) {
            const int a = sRow[m] + k * 3;
            q  = g_QKV[a]     * SCALE;
            kk = g_QKV[a + 1];
            vv = g_QKV[a + 2];
        }
        Qs[m][k] = wmma::__float_to_tf32(q);
        Ks[m][k] = wmma::__float_to_tf32(kk);
        Vs[m][k] = wmma::__float_to_tf32(vv);
    }
    __syncthreads();

    // S = Q @ K^T
    wmma::fragment<wmma::accumulator, 16, 16, 8, float> sfr[4];
    #pragma unroll
    for (int f = 0; f < 4; f++) wmma::fill_fragment(sfr[f], 0.f);
    #pragma unroll
    for (int ks = 0; ks < EH; ks += 8) {
        wmma::fragment<wmma::matrix_a, 16, 16, 8, wmma::precision::tf32, wmma::row_major> a;
        wmma::load_matrix_sync(a, &Qs[m0][ks], 36);
        #pragma unroll
        for (int f = 0; f < 4; f++) {
            wmma::fragment<wmma::matrix_b, 16, 16, 8, wmma::precision::tf32, wmma::col_major> bf;
            wmma::load_matrix_sync(bf, &Ks[f * 16][ks], 36);
            wmma::mma_sync(sfr[f], a, bf, sfr[f]);
        }
    }
    __syncthreads();
    #pragma unroll
    for (int f = 0; f < 4; f++)
        wmma::store_matrix_sync(&Ss[m0][f * 16], sfr[f], 68, wmma::mem_row_major);
    __syncthreads();

    // Masked softmax over valid cols [0,49)
    const bool lastRow = (wh == 7);
    const bool lastCol = (ww == 7);
    for (int m = w; m < WS2; m += 4) {
        const int c1 = lane + 32;
        float s0 = Ss[m][lane];
        float s1 = (lane < 17) ? Ss[m][c1] : -1e30f;
        const bool mr = (m / 7 >= 4), mc = (m % 7 >= 4);
        if ((lastRow && (mr != (lane / 7 >= 4))) ||
            (lastCol && (mc != (lane % 7 >= 4)))) s0 = -1e30f;
        if (lane < 17) {
            if ((lastRow && (mr != (c1 / 7 >= 4))) ||
                (lastCol && (mc != (c1 % 7 >= 4)))) s1 = -1e30f;
        }
        float mx = fmaxf(s0, s1);
        #pragma unroll
        for (int off = 16; off > 0; off >>= 1)
            mx = fmaxf(mx, __shfl_xor_sync(0xffffffff, mx, off));
        float e0 = __expf(s0 - mx);
        float e1 = (lane < 17) ? __expf(s1 - mx) : 0.f;
        float smv = e0 + e1;
        #pragma unroll
        for (int off = 16; off > 0; off >>= 1)
            smv += __shfl_xor_sync(0xffffffff, smv, off);
        const float inv = __frcp_rn(smv);
        Ss[m][lane] = wmma::__float_to_tf32(e0 * inv);
        if (lane < 17) Ss[m][c1] = wmma::__float_to_tf32(e1 * inv);
    }
    __syncthreads();

    // O = P @ V
    wmma::fragment<wmma::accumulator, 16, 16, 8, float> ofr[2];
    #pragma unroll
    for (int f = 0; f < 2; f++) wmma::fill_fragment(ofr[f], 0.f);
    #pragma unroll
    for (int ks = 0; ks < 64; ks += 8) {
        wmma::fragment<wmma::matrix_a, 16, 16, 8, wmma::precision::tf32, wmma::row_major> a;
        wmma::load_matrix_sync(a, &Ss[m0][ks], 68);
        #pragma unroll
        for (int f = 0; f < 2; f++) {
            wmma::fragment<wmma::matrix_b, 16, 16, 8, wmma::precision::tf32, wmma::row_major> bf;
            wmma::load_matrix_sync(bf, &Vs[ks][f * 16], 36);
            wmma::mma_sync(ofr[f], a, bf, ofr[f]);
        }
    }
    __syncthreads();
    #pragma unroll
    for (int f = 0; f < 2; f++)
        wmma::store_matrix_sync(&Os[m0][f * 16], ofr[f], 36, wmma::mem_row_major);
    __syncthreads();

    // Scatter with inverse roll(+3,+3), coalesced 128B per (warp,row)
    for (int idx = t; idx < WS2 * EH; idx += 128) {
        const int m = idx >> 5, eh = idx & 31;
        const int m1 = m / 7, m2 = m % 7;
        const int y  = (wh * WS + m1 + 3) % HW;
        const int xx = (ww * WS + m2 + 3) % HW;
        g_O[(b * SEQ + y * HW + xx) * EMB + head * EH + eh] = Os[m][eh];
    }
}

// ---------------------------------------------------------------------------
// K3: out = O @ w2^T + b2 via mma.sync tf32, dense coalesced write.
// ---------------------------------------------------------------------------
__global__ __launch_bounds__(256) void k_proj(const float* __restrict__ w2,
                                              const float* __restrict__ b2,
                                              float* __restrict__ out) {
    __shared__ float As[6144];
    __shared__ float Bs[4608];

    const int M0 = blockIdx.x * 128;
    const int t = threadIdx.x;
    const int lane = t & 31;
    const int w = t >> 5;
    const int mw = w >> 1;
    const int nw = w & 1;
    const int gID = lane >> 2;
    const int tig = lane & 3;

    const int rA = t >> 1, halfA = t & 1;
    const int gA = rA >> 4, rrA = rA & 15;
    const int fbaseA = gA * 768 + (rrA & 7) * 16 + (rrA >> 3);
    const int ks0A = halfA * 3;
    const int nB = t >> 1, halfB = t & 1;
    const int fbaseB = (nB >> 3) * 64 + (nB & 7) * 8;
    const int ks0B = halfB * 3;

    float d[2][6][4];
    #pragma unroll
    for (int f = 0; f < 2; f++)
        #pragma unroll
        for (int nb = 0; nb < 6; nb++)
            #pragma unroll
            for (int c = 0; c < 4; c++) d[f][nb][c] = 0.f;

    for (int kc = 0; kc < 96; kc += 48) {
        __syncthreads();
        {
            const float* orow = &g_O[(M0 + rA) * 96 + kc + halfA * 24];
            #pragma unroll
            for (int j = 0; j < 6; j++) {
                const float4 v = *(const float4*)&orow[j * 4];
                const int base = fbaseA + (ks0A + (j >> 1)) * 128 + 2 * (j & 1);
                As[base + 0]  = wmma::__float_to_tf32(v.x);
                As[base + 4]  = wmma::__float_to_tf32(v.y);
                As[base + 8]  = wmma::__float_to_tf32(v.z);
                As[base + 12] = wmma::__float_to_tf32(v.w);
            }
        }
        if (t < 192) {
            const float* wrow = &w2[nB * 96 + kc + halfB * 24];
            #pragma unroll
            for (int j = 0; j < 6; j++) {
                const float4 v = *(const float4*)&wrow[j * 4];
                const int base = fbaseB + (ks0B + (j >> 1)) * 768 + (j & 1);
                Bs[base + 0] = wmma::__float_to_tf32(v.x);
                Bs[base + 2] = wmma::__float_to_tf32(v.y);
                Bs[base + 4] = wmma::__float_to_tf32(v.z);
                Bs[base + 6] = wmma::__float_to_tf32(v.w);
            }
        }
        __syncthreads();

        const float4* A4 = (const float4*)As;
        const float2* B2 = (const float2*)Bs;
        #pragma unroll
        for (int ks = 0; ks < 6; ks++) {
            const float4 a0 = A4[((mw * 2 + 0) * 6 + ks) * 32 + lane];
            const float4 a1 = A4[((mw * 2 + 1) * 6 + ks) * 32 + lane];
            float2 bf[6];
            #pragma unroll
            for (int nb = 0; nb < 6; nb++)
                bf[nb] = B2[(ks * 12 + nw * 6 + nb) * 32 + lane];
            #pragma unroll
            for (int nb = 0; nb < 6; nb++) {
                mma_tf32(d[0][nb][0], d[0][nb][1], d[0][nb][2], d[0][nb][3],
                         __float_as_uint(a0.x), __float_as_uint(a0.y),
                         __float_as_uint(a0.z), __float_as_uint(a0.w),
                         __float_as_uint(bf[nb].x), __float_as_uint(bf[nb].y));
                mma_tf32(d[1][nb][0], d[1][nb][1], d[1][nb][2], d[1][nb][3],
                         __float_as_uint(a1.x), __float_as_uint(a1.y),
                         __float_as_uint(a1.z), __float_as_uint(a1.w),
                         __float_as_uint(bf[nb].x), __float_as_uint(bf[nb].y));
            }
        }
    }

    #pragma unroll
    for (int f = 0; f < 2; f++) {
        #pragma unroll
        for (int h = 0; h < 2; h++) {
            const int row = M0 + mw * 32 + f * 16 + gID + 8 * h;
            #pragma unroll
            for (int nb = 0; nb < 6; nb++) {
                const int colp = nw * 48 + nb * 8 + tig * 2;
                float2 o;
                o.x = d[f][nb][h * 2 + 0] + __ldg(&b2[colp]);
                o.y = d[f][nb][h * 2 + 1] + __ldg(&b2[colp + 1]);
                *(float2*)&out[row * 96 + colp] = o;
            }
        }
    }
}

// ---------------------------------------------------------------------------
extern "C" void kernel_launch(void* const* d_in, const int* in_sizes, int n_in,
                              void* d_out, int out_size) {
    const float* x  = (const float*)d_in[0];
    const float* w1 = (const float*)d_in[1];
    const float* b1 = (const float*)d_in[2];
    const float* w2 = (const float*)d_in[3];
    const float* b2 = (const float*)d_in[4];
    float* out = (float*)d_out;

    dim3 g1(SEQ * BATCH / 128, 3);
    k_qkv<<<g1, 256>>>(x, w1, b1);
    k_attn<<<BATCH * HEADS * NWIN, 128>>>();
    k_proj<<<SEQ * BATCH / 128, 256>>>(w2, b2, out);
}

// round 12
// speedup vs baseline: 1.2573x; 1.2573x over previous
#include <cuda_runtime.h>
#include <mma.h>
#include <math.h>

using namespace nvcuda;

#define BATCH 64
#define HW    56
#define SEQ   3136
#define EMB   96
#define HEADS 3
#define EH    32
#define WS    7
#define WS2   49
#define NWIN  64
#define N3E   288

#define SCALE 0.17677669529663687f  // 1/sqrt(32)

#define SLOT_STRIDE 1544   // floats; 6176B, 16B-aligned, +8 bank skew per slot

// Scratch (device globals)
__device__ float g_QKV[BATCH * SEQ * N3E];   // dense [row][288]
__device__ float g_O[BATCH * SEQ * EMB];
// Pre-transposed tf32 weights in MMA fragment-major layout:
// w1f: [ct(3)][chunk(2)][ks(6)][nblk(12)][lane(32)][r(2)]
// w2f: [chunk(2)][ks(6)][nblk(12)][lane(32)][r(2)]
__device__ float g_W1f[3 * 2 * 6 * 12 * 32 * 2];
__device__ float g_W2f[2 * 6 * 12 * 32 * 2];

__device__ __forceinline__ void mma_tf32(float& d0, float& d1, float& d2, float& d3,
                                         unsigned a0, unsigned a1, unsigned a2, unsigned a3,
                                         unsigned b0, unsigned b1) {
    asm volatile(
        "mma.sync.aligned.m16n8k8.row.col.f32.tf32.tf32.f32 "
        "{%0,%1,%2,%3}, {%4,%5,%6,%7}, {%8,%9}, {%0,%1,%2,%3};\n"
        : "+f"(d0), "+f"(d1), "+f"(d2), "+f"(d3)
        : "r"(a0), "r"(a1), "r"(a2), "r"(a3), "r"(b0), "r"(b1));
}

// ---------------------------------------------------------------------------
// K0: pre-transpose w1/w2 into tf32 fragment-major layout (tiny).
// ---------------------------------------------------------------------------
__global__ __launch_bounds__(256) void k_prep(const float* __restrict__ w1,
                                              const float* __restrict__ w2) {
    int idx = blockIdx.x * 256 + threadIdx.x;
    if (idx < 27648) {
        const int r = idx & 1;
        const int lane = (idx >> 1) & 31;
        int rest = idx >> 6;
        const int nblk = rest % 12; rest /= 12;
        const int ks = rest % 6; rest /= 6;
        const int chunk = rest & 1;
        const int ct = rest >> 1;
        const int n = ct * 96 + nblk * 8 + (lane >> 2);
        const int k = chunk * 48 + ks * 8 + r * 4 + (lane & 3);
        g_W1f[idx] = wmma::__float_to_tf32(w1[n * 96 + k]);
    } else {
        int i2 = idx - 27648;
        if (i2 < 9216) {
            const int r = i2 & 1;
            const int lane = (i2 >> 1) & 31;
            int rest = i2 >> 6;
            const int nblk = rest % 12; rest /= 12;
            const int ks = rest % 6; rest /= 6;
            const int chunk = rest & 1;
            const int n = nblk * 8 + (lane >> 2);
            const int k = chunk * 48 + ks * 8 + r * 4 + (lane & 3);
            g_W2f[i2] = wmma::__float_to_tf32(w2[n * 96 + k]);
        }
    }
}

// ---------------------------------------------------------------------------
// K1: qkv = x @ w1^T + b1 via mma.sync tf32. Dense output [row][288].
// A staged slot-major with 16B-aligned, conflict-free STS.128;
// B via coalesced LDG.64 from fragment-major g_W1f (no SMEM for B).
// Block tile 128(M) x 96(N) (blockIdx.y = ct). 256 thr = 8 warps (4x2).
// ---------------------------------------------------------------------------
__global__ __launch_bounds__(256) void k_qkv(const float* __restrict__ x,
                                             const float* __restrict__ b1) {
    __shared__ __align__(16) float Asl[4 * SLOT_STRIDE];

    const int M0 = blockIdx.x * 128;
    const int ct = blockIdx.y;
    const int c0 = ct * 96;
    const int t = threadIdx.x;
    const int lane = t & 31;
    const int w = t >> 5;
    const int mw = w >> 1;
    const int nw = w & 1;
    const int gID = lane >> 2;
    const int tig = lane & 3;

    // A staging: 256 threads = 128 rows x 2 slot-parities (e)
    const int rA = t >> 1, e = t & 1;
    const int gA = rA >> 4, rrA = rA & 15;
    const int slotA = (rrA >> 3) + 2 * e;      // fixed per thread
    const int Lb = (rrA & 7) * 4;
    const int Fb = gA * 6;                     // + j per segment

    const float2* Wf = (const float2*)g_W1f;

    float d[2][6][4];
    #pragma unroll
    for (int f = 0; f < 2; f++)
        #pragma unroll
        for (int nb = 0; nb < 6; nb++)
            #pragma unroll
            for (int c = 0; c < 4; c++) d[f][nb][c] = 0.f;

    for (int chunk = 0; chunk < 2; chunk++) {
        __syncthreads();
        // Stage A chunk [128 x 48]: thread (rA,e) writes 6 float4 (j=0..5)
        // at col 8j+4e, slot = slotA, F = Fb+j.  STS.128, conflict-free.
        {
            const float* xrow = &x[(M0 + rA) * 96 + chunk * 48 + 4 * e];
            float* dstBase = &Asl[slotA * SLOT_STRIDE + Lb];
            #pragma unroll
            for (int j = 0; j < 6; j++) {
                const float4 v = *(const float4*)&xrow[8 * j];
                float4 o;
                o.x = wmma::__float_to_tf32(v.x);
                o.y = wmma::__float_to_tf32(v.y);
                o.z = wmma::__float_to_tf32(v.z);
                o.w = wmma::__float_to_tf32(v.w);
                *(float4*)&dstBase[(Fb + j) * 32] = o;
            }
        }
        __syncthreads();

        const float2* Wc = Wf + ((size_t)(ct * 2 + chunk)) * 2304 + (nw * 6) * 32 + lane;
        #pragma unroll
        for (int ks = 0; ks < 6; ks++) {
            const int F0 = ((mw * 2 + 0) * 6 + ks) * 32 + lane;
            const int F1 = ((mw * 2 + 1) * 6 + ks) * 32 + lane;
            unsigned a00 = __float_as_uint(Asl[0 * SLOT_STRIDE + F0]);
            unsigned a01 = __float_as_uint(Asl[1 * SLOT_STRIDE + F0]);
            unsigned a02 = __float_as_uint(Asl[2 * SLOT_STRIDE + F0]);
            unsigned a03 = __float_as_uint(Asl[3 * SLOT_STRIDE + F0]);
            unsigned a10 = __float_as_uint(Asl[0 * SLOT_STRIDE + F1]);
            unsigned a11 = __float_as_uint(Asl[1 * SLOT_STRIDE + F1]);
            unsigned a12 = __float_as_uint(Asl[2 * SLOT_STRIDE + F1]);
            unsigned a13 = __float_as_uint(Asl[3 * SLOT_STRIDE + F1]);
            float2 bf[6];
            #pragma unroll
            for (int nb = 0; nb < 6; nb++)
                bf[nb] = __ldg(&Wc[(ks * 12 + nb) * 32]);
            #pragma unroll
            for (int nb = 0; nb < 6; nb++) {
                mma_tf32(d[0][nb][0], d[0][nb][1], d[0][nb][2], d[0][nb][3],
                         a00, a01, a02, a03,
                         __float_as_uint(bf[nb].x), __float_as_uint(bf[nb].y));
                mma_tf32(d[1][nb][0], d[1][nb][1], d[1][nb][2], d[1][nb][3],
                         a10, a11, a12, a13,
                         __float_as_uint(bf[nb].x), __float_as_uint(bf[nb].y));
            }
        }
    }

    // Dense epilogue: float2 stores straight from registers
    #pragma unroll
    for (int f = 0; f < 2; f++) {
        #pragma unroll
        for (int h = 0; h < 2; h++) {
            const int row = M0 + mw * 32 + f * 16 + gID + 8 * h;
            #pragma unroll
            for (int nb = 0; nb < 6; nb++) {
                const int colp = nw * 48 + nb * 8 + tig * 2;
                float2 o;
                o.x = d[f][nb][h * 2 + 0] + __ldg(&b1[c0 + colp]);
                o.y = d[f][nb][h * 2 + 1] + __ldg(&b1[c0 + colp + 1]);
                *(float2*)&g_QKV[row * N3E + c0 + colp] = o;
            }
        }
    }
}

// ---------------------------------------------------------------------------
// K2: window attention. Gathers Q/K/V from dense g_QKV via sRow[] map.
// One block per (b, head, window), 128 threads.
// ---------------------------------------------------------------------------
__global__ __launch_bounds__(128) void k_attn() {
    __shared__ float sm[6912];
    __shared__ int sRow[WS2];
    float (*Qs)[36] = (float(*)[36])sm;
    float (*Ks)[36] = (float(*)[36])(sm + 2304);
    float (*Vs)[36] = (float(*)[36])(sm + 4608);
    float (*Ss)[68] = (float(*)[68])sm;
    float (*Os)[36] = (float(*)[36])sm;

    const int blk = blockIdx.x;
    const int win = blk & 63;
    const int head = (blk >> 6) % 3;
    const int b = blk / (NWIN * HEADS);
    const int t = threadIdx.x;
    const int w = t >> 5, lane = t & 31;
    const int m0 = w * 16;
    const int wh = win >> 3, ww = win & 7;

    if (t < WS2) {
        const int m1 = t / 7, m2 = t % 7;
        const int y  = (wh * WS + m1 + 4) % HW;
        const int xx = (ww * WS + m2 + 4) % HW;
        sRow[t] = (b * SEQ + y * HW + xx) * N3E + head * 96;
    }
    __syncthreads();

    for (int i = t; i < 64 * EH; i += 128) {
        const int m = i >> 5, k = i & 31;
        float q = 0.f, kk = 0.f, vv = 0.f;
        if (m < WS2) {
            const int a = sRow[m] + k * 3;
            q  = g_QKV[a]     * SCALE;
            kk = g_QKV[a + 1];
            vv = g_QKV[a + 2];
        }
        Qs[m][k] = wmma::__float_to_tf32(q);
        Ks[m][k] = wmma::__float_to_tf32(kk);
        Vs[m][k] = wmma::__float_to_tf32(vv);
    }
    __syncthreads();

    wmma::fragment<wmma::accumulator, 16, 16, 8, float> sfr[4];
    #pragma unroll
    for (int f = 0; f < 4; f++) wmma::fill_fragment(sfr[f], 0.f);
    #pragma unroll
    for (int ks = 0; ks < EH; ks += 8) {
        wmma::fragment<wmma::matrix_a, 16, 16, 8, wmma::precision::tf32, wmma::row_major> a;
        wmma::load_matrix_sync(a, &Qs[m0][ks], 36);
        #pragma unroll
        for (int f = 0; f < 4; f++) {
            wmma::fragment<wmma::matrix_b, 16, 16, 8, wmma::precision::tf32, wmma::col_major> bf;
            wmma::load_matrix_sync(bf, &Ks[f * 16][ks], 36);
            wmma::mma_sync(sfr[f], a, bf, sfr[f]);
        }
    }
    __syncthreads();
    #pragma unroll
    for (int f = 0; f < 4; f++)
        wmma::store_matrix_sync(&Ss[m0][f * 16], sfr[f], 68, wmma::mem_row_major);
    __syncthreads();

    const bool lastRow = (wh == 7);
    const bool lastCol = (ww == 7);
    for (int m = w; m < WS2; m += 4) {
        const int c1 = lane + 32;
        float s0 = Ss[m][lane];
        float s1 = (lane < 17) ? Ss[m][c1] : -1e30f;
        const bool mr = (m / 7 >= 4), mc = (m % 7 >= 4);
        if ((lastRow && (mr != (lane / 7 >= 4))) ||
            (lastCol && (mc != (lane % 7 >= 4)))) s0 = -1e30f;
        if (lane < 17) {
            if ((lastRow && (mr != (c1 / 7 >= 4))) ||
                (lastCol && (mc != (c1 % 7 >= 4)))) s1 = -1e30f;
        }
        float mx = fmaxf(s0, s1);
        #pragma unroll
        for (int off = 16; off > 0; off >>= 1)
            mx = fmaxf(mx, __shfl_xor_sync(0xffffffff, mx, off));
        float e0 = __expf(s0 - mx);
        float e1 = (lane < 17) ? __expf(s1 - mx) : 0.f;
        float smv = e0 + e1;
        #pragma unroll
        for (int off = 16; off > 0; off >>= 1)
            smv += __shfl_xor_sync(0xffffffff, smv, off);
        const float inv = __frcp_rn(smv);
        Ss[m][lane] = wmma::__float_to_tf32(e0 * inv);
        if (lane < 17) Ss[m][c1] = wmma::__float_to_tf32(e1 * inv);
    }
    __syncthreads();

    wmma::fragment<wmma::accumulator, 16, 16, 8, float> ofr[2];
    #pragma unroll
    for (int f = 0; f < 2; f++) wmma::fill_fragment(ofr[f], 0.f);
    #pragma unroll
    for (int ks = 0; ks < 64; ks += 8) {
        wmma::fragment<wmma::matrix_a, 16, 16, 8, wmma::precision::tf32, wmma::row_major> a;
        wmma::load_matrix_sync(a, &Ss[m0][ks], 68);
        #pragma unroll
        for (int f = 0; f < 2; f++) {
            wmma::fragment<wmma::matrix_b, 16, 16, 8, wmma::precision::tf32, wmma::row_major> bf;
            wmma::load_matrix_sync(bf, &Vs[ks][f * 16], 36);
            wmma::mma_sync(ofr[f], a, bf, ofr[f]);
        }
    }
    __syncthreads();
    #pragma unroll
    for (int f = 0; f < 2; f++)
        wmma::store_matrix_sync(&Os[m0][f * 16], ofr[f], 36, wmma::mem_row_major);
    __syncthreads();

    for (int idx = t; idx < WS2 * EH; idx += 128) {
        const int m = idx >> 5, eh = idx & 31;
        const int m1 = m / 7, m2 = m % 7;
        const int y  = (wh * WS + m1 + 3) % HW;
        const int xx = (ww * WS + m2 + 3) % HW;
        g_O[(b * SEQ + y * HW + xx) * EMB + head * EH + eh] = Os[m][eh];
    }
}

// ---------------------------------------------------------------------------
// K3: out = O @ w2^T + b2. Same structure as K1, dense coalesced write.
// ---------------------------------------------------------------------------
__global__ __launch_bounds__(256) void k_proj(const float* __restrict__ b2,
                                              float* __restrict__ out) {
    __shared__ __align__(16) float Asl[4 * SLOT_STRIDE];

    const int M0 = blockIdx.x * 128;
    const int t = threadIdx.x;
    const int lane = t & 31;
    const int w = t >> 5;
    const int mw = w >> 1;
    const int nw = w & 1;
    const int gID = lane >> 2;
    const int tig = lane & 3;

    const int rA = t >> 1, e = t & 1;
    const int gA = rA >> 4, rrA = rA & 15;
    const int slotA = (rrA >> 3) + 2 * e;
    const int Lb = (rrA & 7) * 4;
    const int Fb = gA * 6;

    const float2* Wf = (const float2*)g_W2f;

    float d[2][6][4];
    #pragma unroll
    for (int f = 0; f < 2; f++)
        #pragma unroll
        for (int nb = 0; nb < 6; nb++)
            #pragma unroll
            for (int c = 0; c < 4; c++) d[f][nb][c] = 0.f;

    for (int chunk = 0; chunk < 2; chunk++) {
        __syncthreads();
        {
            const float* orow = &g_O[(M0 + rA) * 96 + chunk * 48 + 4 * e];
            float* dstBase = &Asl[slotA * SLOT_STRIDE + Lb];
            #pragma unroll
            for (int j = 0; j < 6; j++) {
                const float4 v = *(const float4*)&orow[8 * j];
                float4 o;
                o.x = wmma::__float_to_tf32(v.x);
                o.y = wmma::__float_to_tf32(v.y);
                o.z = wmma::__float_to_tf32(v.z);
                o.w = wmma::__float_to_tf32(v.w);
                *(float4*)&dstBase[(Fb + j) * 32] = o;
            }
        }
        __syncthreads();

        const float2* Wc = Wf + ((size_t)chunk) * 2304 + (nw * 6) * 32 + lane;
        #pragma unroll
        for (int ks = 0; ks < 6; ks++) {
            const int F0 = ((mw * 2 + 0) * 6 + ks) * 32 + lane;
            const int F1 = ((mw * 2 + 1) * 6 + ks) * 32 + lane;
            unsigned a00 = __float_as_uint(Asl[0 * SLOT_STRIDE + F0]);
            unsigned a01 = __float_as_uint(Asl[1 * SLOT_STRIDE + F0]);
            unsigned a02 = __float_as_uint(Asl[2 * SLOT_STRIDE + F0]);
            unsigned a03 = __float_as_uint(Asl[3 * SLOT_STRIDE + F0]);
            unsigned a10 = __float_as_uint(Asl[0 * SLOT_STRIDE + F1]);
            unsigned a11 = __float_as_uint(Asl[1 * SLOT_STRIDE + F1]);
            unsigned a12 = __float_as_uint(Asl[2 * SLOT_STRIDE + F1]);
            unsigned a13 = __float_as_uint(Asl[3 * SLOT_STRIDE + F1]);
            float2 bf[6];
            #pragma unroll
            for (int nb = 0; nb < 6; nb++)
                bf[nb] = __ldg(&Wc[(ks * 12 + nb) * 32]);
            #pragma unroll
            for (int nb = 0; nb < 6; nb++) {
                mma_tf32(d[0][nb][0], d[0][nb][1], d[0][nb][2], d[0][nb][3],
                         a00, a01, a02, a03,
                         __float_as_uint(bf[nb].x), __float_as_uint(bf[nb].y));
                mma_tf32(d[1][nb][0], d[1][nb][1], d[1][nb][2], d[1][nb][3],
                         a10, a11, a12, a13,
                         __float_as_uint(bf[nb].x), __float_as_uint(bf[nb].y));
            }
        }
    }

    #pragma unroll
    for (int f = 0; f < 2; f++) {
        #pragma unroll
        for (int h = 0; h < 2; h++) {
            const int row = M0 + mw * 32 + f * 16 + gID + 8 * h;
            #pragma unroll
            for (int nb = 0; nb < 6; nb++) {
                const int colp = nw * 48 + nb * 8 + tig * 2;
                float2 o;
                o.x = d[f][nb][h * 2 + 0] + __ldg(&b2[colp]);
                o.y = d[f][nb][h * 2 + 1] + __ldg(&b2[colp + 1]);
                *(float2*)&out[row * 96 + colp] = o;
            }
        }
    }
}

// ---------------------------------------------------------------------------
extern "C" void kernel_launch(void* const* d_in, const int* in_sizes, int n_in,
                              void* d_out, int out_size) {
    const float* x  = (const float*)d_in[0];
    const float* w1 = (const float*)d_in[1];
    const float* b1 = (const float*)d_in[2];
    const float* w2 = (const float*)d_in[3];
    const float* b2 = (const float*)d_in[4];
    float* out = (float*)d_out;

    k_prep<<<144, 256>>>(w1, w2);
    dim3 g1(SEQ * BATCH / 128, 3);
    k_qkv<<<g1, 256>>>(x, b1);
    k_attn<<<BATCH * HEADS * NWIN, 128>>>();
    k_proj<<<SEQ * BATCH / 128, 256>>>(b2, out);
}

// round 13
// speedup vs baseline: 1.7229x; 1.3704x over previous
#include <cuda_runtime.h>
#include <mma.h>
#include <math.h>

using namespace nvcuda;

#define BATCH 64
#define HW    56
#define SEQ   3136
#define EMB   96
#define HEADS 3
#define EH    32
#define WS    7
#define WS2   49
#define NWIN  64
#define N3E   288

#define SCALE 0.17677669529663687f  // 1/sqrt(32)

#define SLOT_STRIDE 1544   // floats; 6176B, 16B-aligned, +8 bank skew per slot

// Scratch (device globals)
__device__ float g_QKV[BATCH * SEQ * N3E];   // dense [row][288]
__device__ float g_O[BATCH * SEQ * EMB];
// Pre-transposed tf32 weights in MMA fragment-major layout:
__device__ float g_W1f[3 * 2 * 6 * 12 * 32 * 2];
__device__ float g_W2f[2 * 6 * 12 * 32 * 2];

__device__ __forceinline__ void mma_tf32(float& d0, float& d1, float& d2, float& d3,
                                         unsigned a0, unsigned a1, unsigned a2, unsigned a3,
                                         unsigned b0, unsigned b1) {
    asm volatile(
        "mma.sync.aligned.m16n8k8.row.col.f32.tf32.tf32.f32 "
        "{%0,%1,%2,%3}, {%4,%5,%6,%7}, {%8,%9}, {%0,%1,%2,%3};\n"
        : "+f"(d0), "+f"(d1), "+f"(d2), "+f"(d3)
        : "r"(a0), "r"(a1), "r"(a2), "r"(a3), "r"(b0), "r"(b1));
}

// ---------------------------------------------------------------------------
// K0: pre-transpose w1/w2 into tf32 fragment-major layout (tiny).
// ---------------------------------------------------------------------------
__global__ __launch_bounds__(256) void k_prep(const float* __restrict__ w1,
                                              const float* __restrict__ w2) {
    int idx = blockIdx.x * 256 + threadIdx.x;
    if (idx < 27648) {
        const int r = idx & 1;
        const int lane = (idx >> 1) & 31;
        int rest = idx >> 6;
        const int nblk = rest % 12; rest /= 12;
        const int ks = rest % 6; rest /= 6;
        const int chunk = rest & 1;
        const int ct = rest >> 1;
        const int n = ct * 96 + nblk * 8 + (lane >> 2);
        const int k = chunk * 48 + ks * 8 + r * 4 + (lane & 3);
        g_W1f[idx] = wmma::__float_to_tf32(w1[n * 96 + k]);
    } else {
        int i2 = idx - 27648;
        if (i2 < 9216) {
            const int r = i2 & 1;
            const int lane = (i2 >> 1) & 31;
            int rest = i2 >> 6;
            const int nblk = rest % 12; rest /= 12;
            const int ks = rest % 6; rest /= 6;
            const int chunk = rest & 1;
            const int n = nblk * 8 + (lane >> 2);
            const int k = chunk * 48 + ks * 8 + r * 4 + (lane & 3);
            g_W2f[i2] = wmma::__float_to_tf32(w2[n * 96 + k]);
        }
    }
}

// ---------------------------------------------------------------------------
// K1: qkv = x @ w1^T + b1 via mma.sync tf32 (unchanged from R12).
// ---------------------------------------------------------------------------
__global__ __launch_bounds__(256) void k_qkv(const float* __restrict__ x,
                                             const float* __restrict__ b1) {
    __shared__ __align__(16) float Asl[4 * SLOT_STRIDE];

    const int M0 = blockIdx.x * 128;
    const int ct = blockIdx.y;
    const int c0 = ct * 96;
    const int t = threadIdx.x;
    const int lane = t & 31;
    const int w = t >> 5;
    const int mw = w >> 1;
    const int nw = w & 1;
    const int gID = lane >> 2;
    const int tig = lane & 3;

    const int rA = t >> 1, e = t & 1;
    const int gA = rA >> 4, rrA = rA & 15;
    const int slotA = (rrA >> 3) + 2 * e;
    const int Lb = (rrA & 7) * 4;
    const int Fb = gA * 6;

    const float2* Wf = (const float2*)g_W1f;

    float d[2][6][4];
    #pragma unroll
    for (int f = 0; f < 2; f++)
        #pragma unroll
        for (int nb = 0; nb < 6; nb++)
            #pragma unroll
            for (int c = 0; c < 4; c++) d[f][nb][c] = 0.f;

    for (int chunk = 0; chunk < 2; chunk++) {
        __syncthreads();
        {
            const float* xrow = &x[(M0 + rA) * 96 + chunk * 48 + 4 * e];
            float* dstBase = &Asl[slotA * SLOT_STRIDE + Lb];
            #pragma unroll
            for (int j = 0; j < 6; j++) {
                const float4 v = *(const float4*)&xrow[8 * j];
                float4 o;
                o.x = wmma::__float_to_tf32(v.x);
                o.y = wmma::__float_to_tf32(v.y);
                o.z = wmma::__float_to_tf32(v.z);
                o.w = wmma::__float_to_tf32(v.w);
                *(float4*)&dstBase[(Fb + j) * 32] = o;
            }
        }
        __syncthreads();

        const float2* Wc = Wf + ((size_t)(ct * 2 + chunk)) * 2304 + (nw * 6) * 32 + lane;
        #pragma unroll
        for (int ks = 0; ks < 6; ks++) {
            const int F0 = ((mw * 2 + 0) * 6 + ks) * 32 + lane;
            const int F1 = ((mw * 2 + 1) * 6 + ks) * 32 + lane;
            unsigned a00 = __float_as_uint(Asl[0 * SLOT_STRIDE + F0]);
            unsigned a01 = __float_as_uint(Asl[1 * SLOT_STRIDE + F0]);
            unsigned a02 = __float_as_uint(Asl[2 * SLOT_STRIDE + F0]);
            unsigned a03 = __float_as_uint(Asl[3 * SLOT_STRIDE + F0]);
            unsigned a10 = __float_as_uint(Asl[0 * SLOT_STRIDE + F1]);
            unsigned a11 = __float_as_uint(Asl[1 * SLOT_STRIDE + F1]);
            unsigned a12 = __float_as_uint(Asl[2 * SLOT_STRIDE + F1]);
            unsigned a13 = __float_as_uint(Asl[3 * SLOT_STRIDE + F1]);
            float2 bf[6];
            #pragma unroll
            for (int nb = 0; nb < 6; nb++)
                bf[nb] = __ldg(&Wc[(ks * 12 + nb) * 32]);
            #pragma unroll
            for (int nb = 0; nb < 6; nb++) {
                mma_tf32(d[0][nb][0], d[0][nb][1], d[0][nb][2], d[0][nb][3],
                         a00, a01, a02, a03,
                         __float_as_uint(bf[nb].x), __float_as_uint(bf[nb].y));
                mma_tf32(d[1][nb][0], d[1][nb][1], d[1][nb][2], d[1][nb][3],
                         a10, a11, a12, a13,
                         __float_as_uint(bf[nb].x), __float_as_uint(bf[nb].y));
            }
        }
    }

    #pragma unroll
    for (int f = 0; f < 2; f++) {
        #pragma unroll
        for (int h = 0; h < 2; h++) {
            const int row = M0 + mw * 32 + f * 16 + gID + 8 * h;
            #pragma unroll
            for (int nb = 0; nb < 6; nb++) {
                const int colp = nw * 48 + nb * 8 + tig * 2;
                float2 o;
                o.x = d[f][nb][h * 2 + 0] + __ldg(&b1[c0 + colp]);
                o.y = d[f][nb][h * 2 + 1] + __ldg(&b1[c0 + colp + 1]);
                *(float2*)&g_QKV[row * N3E + c0 + colp] = o;
            }
        }
    }
}

// ---------------------------------------------------------------------------
// K2 (REWRITTEN): window attention via raw mma.sync m16n8k8 tf32.
// - S accumulators stay in registers; masks + softmax in registers
//   (row = 4-lane tig-quad -> 2x shfl_xor reductions).
// - P staged per-warp (16x68, overlays dead Q/K smem), consumed under
//   __syncwarp only. Conflict-free A reads (stride 68 = 4 mod 32).
// - O written straight from PV accumulators via oRow[] (inverse roll).
// 3 block barriers total. One block per (b, head, window), 128 threads.
// ---------------------------------------------------------------------------
__global__ __launch_bounds__(128) void k_attn() {
    __shared__ __align__(16) float sm[3 * 64 * 36];   // Qs|Ks|Vs ; P overlays Qs+Ks
    __shared__ int sRow[WS2];
    __shared__ int oRow[WS2];
    float (*Qs)[36] = (float(*)[36])sm;
    float (*Ks)[36] = (float(*)[36])(sm + 2304);
    float (*Vs)[36] = (float(*)[36])(sm + 4608);

    const int blk = blockIdx.x;
    const int win = blk & 63;
    const int head = (blk >> 6) % 3;
    const int b = blk / (NWIN * HEADS);
    const int t = threadIdx.x;
    const int w = t >> 5, lane = t & 31;
    const int gID = lane >> 2, tig = lane & 3;
    const int m0 = w * 16;
    const int wh = win >> 3, ww = win & 7;

    // Token maps: gather (fwd roll +4) and output (inv roll +3)
    if (t < WS2) {
        const int m1 = t / 7, m2 = t % 7;
        {
            const int y  = (wh * WS + m1 + 4) % HW;
            const int xx = (ww * WS + m2 + 4) % HW;
            sRow[t] = (b * SEQ + y * HW + xx) * N3E + head * 96;
        }
        {
            const int y  = (wh * WS + m1 + 3) % HW;
            const int xx = (ww * WS + m2 + 3) % HW;
            oRow[t] = (b * SEQ + y * HW + xx) * EMB + head * EH;
        }
    }
    __syncthreads();

    // Gather Q(*scale)/K/V from dense g_QKV; zero-pad rows 49..63
    for (int i = t; i < 64 * EH; i += 128) {
        const int m = i >> 5, k = i & 31;
        float q = 0.f, kk = 0.f, vv = 0.f;
        if (m < WS2) {
            const int a = sRow[m] + k * 3;
            q  = g_QKV[a]     * SCALE;
            kk = g_QKV[a + 1];
            vv = g_QKV[a + 2];
        }
        Qs[m][k] = wmma::__float_to_tf32(q);
        Ks[m][k] = wmma::__float_to_tf32(kk);
        Vs[m][k] = wmma::__float_to_tf32(vv);
    }
    __syncthreads();

    // ---- S = Q @ K^T : warp w -> rows m0..m0+15, 8 n-blocks of 8 cols ----
    float c[8][4];
    #pragma unroll
    for (int nb = 0; nb < 8; nb++)
        #pragma unroll
        for (int q = 0; q < 4; q++) c[nb][q] = 0.f;

    #pragma unroll
    for (int ks = 0; ks < 4; ks++) {
        const float* qb = &Qs[m0 + gID][ks * 8 + tig];
        const unsigned a0 = __float_as_uint(qb[0]);
        const unsigned a1 = __float_as_uint(qb[8 * 36]);
        const unsigned a2 = __float_as_uint(qb[4]);
        const unsigned a3 = __float_as_uint(qb[8 * 36 + 4]);
        #pragma unroll
        for (int nb = 0; nb < 8; nb++) {
            const float* kbp = &Ks[nb * 8 + gID][ks * 8 + tig];
            mma_tf32(c[nb][0], c[nb][1], c[nb][2], c[nb][3],
                     a0, a1, a2, a3,
                     __float_as_uint(kbp[0]), __float_as_uint(kbp[4]));
        }
    }

    // ---- masks + softmax in registers ----
    const bool lastRow = (wh == 7);
    const bool lastCol = (ww == 7);
    const int r0 = m0 + gID;
    const int r1 = r0 + 8;
    const bool rD0 = (r0 >= 28), rM0 = (r0 % 7) >= 4;
    const bool rD1 = (r1 >= 28), rM1 = (r1 % 7) >= 4;

    float mx0 = -1e30f, mx1 = -1e30f;
    #pragma unroll
    for (int nb = 0; nb < 8; nb++) {
        #pragma unroll
        for (int bc = 0; bc < 2; bc++) {
            const int col = nb * 8 + 2 * tig + bc;
            const bool cOK = (col < WS2);
            const bool cD = (col >= 28);
            const bool cM = (col % 7) >= 4;
            const bool bad0 = !cOK || (lastRow && (rD0 != cD)) || (lastCol && (rM0 != cM));
            const bool bad1 = !cOK || (lastRow && (rD1 != cD)) || (lastCol && (rM1 != cM));
            if (bad0) c[nb][bc]     = -1e30f;
            if (bad1) c[nb][2 + bc] = -1e30f;
            mx0 = fmaxf(mx0, c[nb][bc]);
            mx1 = fmaxf(mx1, c[nb][2 + bc]);
        }
    }
    mx0 = fmaxf(mx0, __shfl_xor_sync(0xffffffff, mx0, 1));
    mx0 = fmaxf(mx0, __shfl_xor_sync(0xffffffff, mx0, 2));
    mx1 = fmaxf(mx1, __shfl_xor_sync(0xffffffff, mx1, 1));
    mx1 = fmaxf(mx1, __shfl_xor_sync(0xffffffff, mx1, 2));

    float s0 = 0.f, s1 = 0.f;
    #pragma unroll
    for (int nb = 0; nb < 8; nb++) {
        #pragma unroll
        for (int bc = 0; bc < 2; bc++) {
            c[nb][bc]     = __expf(c[nb][bc] - mx0);     s0 += c[nb][bc];
            c[nb][2 + bc] = __expf(c[nb][2 + bc] - mx1); s1 += c[nb][2 + bc];
        }
    }
    s0 += __shfl_xor_sync(0xffffffff, s0, 1);
    s0 += __shfl_xor_sync(0xffffffff, s0, 2);
    s1 += __shfl_xor_sync(0xffffffff, s1, 1);
    s1 += __shfl_xor_sync(0xffffffff, s1, 2);
    const float inv0 = __frcp_rn(s0);
    const float inv1 = __frcp_rn(s1);
    #pragma unroll
    for (int nb = 0; nb < 8; nb++) {
        c[nb][0] = wmma::__float_to_tf32(c[nb][0] * inv0);
        c[nb][1] = wmma::__float_to_tf32(c[nb][1] * inv0);
        c[nb][2] = wmma::__float_to_tf32(c[nb][2] * inv1);
        c[nb][3] = wmma::__float_to_tf32(c[nb][3] * inv1);
    }

    // All warps past S (done reading Qs/Ks) before P overlays them
    __syncthreads();

    // ---- stage P per-warp: 16 x 68 (stride 68 -> conflict-free A reads) ----
    float* Pw = sm + w * 1088;   // 4 warps * 1088 = 4352 <= 4608 (Qs+Ks)
    #pragma unroll
    for (int nb = 0; nb < 8; nb++) {
        *(float2*)&Pw[gID * 68 + nb * 8 + 2 * tig]       = make_float2(c[nb][0], c[nb][1]);
        *(float2*)&Pw[(gID + 8) * 68 + nb * 8 + 2 * tig] = make_float2(c[nb][2], c[nb][3]);
    }
    __syncwarp();

    // ---- O = P @ V : 4 n-blocks of 8 e-cols ----
    float o[4][4];
    #pragma unroll
    for (int nb = 0; nb < 4; nb++)
        #pragma unroll
        for (int q = 0; q < 4; q++) o[nb][q] = 0.f;

    #pragma unroll
    for (int kb = 0; kb < 8; kb++) {
        const float* pb = &Pw[gID * 68 + kb * 8 + tig];
        const unsigned a0 = __float_as_uint(pb[0]);
        const unsigned a1 = __float_as_uint(pb[8 * 68]);
        const unsigned a2 = __float_as_uint(pb[4]);
        const unsigned a3 = __float_as_uint(pb[8 * 68 + 4]);
        #pragma unroll
        for (int nb = 0; nb < 4; nb++) {
            const float* vbp = &Vs[kb * 8 + tig][nb * 8 + gID];
            mma_tf32(o[nb][0], o[nb][1], o[nb][2], o[nb][3],
                     a0, a1, a2, a3,
                     __float_as_uint(vbp[0]), __float_as_uint(vbp[4 * 36]));
        }
    }

    // ---- write O directly (inverse roll via oRow) ----
    if (r0 < WS2) {
        const int base = oRow[r0];
        #pragma unroll
        for (int nb = 0; nb < 4; nb++)
            *(float2*)&g_O[base + nb * 8 + 2 * tig] = make_float2(o[nb][0], o[nb][1]);
    }
    if (r1 < WS2) {
        const int base = oRow[r1];
        #pragma unroll
        for (int nb = 0; nb < 4; nb++)
            *(float2*)&g_O[base + nb * 8 + 2 * tig] = make_float2(o[nb][2], o[nb][3]);
    }
}

// ---------------------------------------------------------------------------
// K3: out = O @ w2^T + b2 (unchanged from R12).
// ---------------------------------------------------------------------------
__global__ __launch_bounds__(256) void k_proj(const float* __restrict__ b2,
                                              float* __restrict__ out) {
    __shared__ __align__(16) float Asl[4 * SLOT_STRIDE];

    const int M0 = blockIdx.x * 128;
    const int t = threadIdx.x;
    const int lane = t & 31;
    const int w = t >> 5;
    const int mw = w >> 1;
    const int nw = w & 1;
    const int gID = lane >> 2;
    const int tig = lane & 3;

    const int rA = t >> 1, e = t & 1;
    const int gA = rA >> 4, rrA = rA & 15;
    const int slotA = (rrA >> 3) + 2 * e;
    const int Lb = (rrA & 7) * 4;
    const int Fb = gA * 6;

    const float2* Wf = (const float2*)g_W2f;

    float d[2][6][4];
    #pragma unroll
    for (int f = 0; f < 2; f++)
        #pragma unroll
        for (int nb = 0; nb < 6; nb++)
            #pragma unroll
            for (int c = 0; c < 4; c++) d[f][nb][c] = 0.f;

    for (int chunk = 0; chunk < 2; chunk++) {
        __syncthreads();
        {
            const float* orow = &g_O[(M0 + rA) * 96 + chunk * 48 + 4 * e];
            float* dstBase = &Asl[slotA * SLOT_STRIDE + Lb];
            #pragma unroll
            for (int j = 0; j < 6; j++) {
                const float4 v = *(const float4*)&orow[8 * j];
                float4 o;
                o.x = wmma::__float_to_tf32(v.x);
                o.y = wmma::__float_to_tf32(v.y);
                o.z = wmma::__float_to_tf32(v.z);
                o.w = wmma::__float_to_tf32(v.w);
                *(float4*)&dstBase[(Fb + j) * 32] = o;
            }
        }
        __syncthreads();

        const float2* Wc = Wf + ((size_t)chunk) * 2304 + (nw * 6) * 32 + lane;
        #pragma unroll
        for (int ks = 0; ks < 6; ks++) {
            const int F0 = ((mw * 2 + 0) * 6 + ks) * 32 + lane;
            const int F1 = ((mw * 2 + 1) * 6 + ks) * 32 + lane;
            unsigned a00 = __float_as_uint(Asl[0 * SLOT_STRIDE + F0]);
            unsigned a01 = __float_as_uint(Asl[1 * SLOT_STRIDE + F0]);
            unsigned a02 = __float_as_uint(Asl[2 * SLOT_STRIDE + F0]);
            unsigned a03 = __float_as_uint(Asl[3 * SLOT_STRIDE + F0]);
            unsigned a10 = __float_as_uint(Asl[0 * SLOT_STRIDE + F1]);
            unsigned a11 = __float_as_uint(Asl[1 * SLOT_STRIDE + F1]);
            unsigned a12 = __float_as_uint(Asl[2 * SLOT_STRIDE + F1]);
            unsigned a13 = __float_as_uint(Asl[3 * SLOT_STRIDE + F1]);
            float2 bf[6];
            #pragma unroll
            for (int nb = 0; nb < 6; nb++)
                bf[nb] = __ldg(&Wc[(ks * 12 + nb) * 32]);
            #pragma unroll
            for (int nb = 0; nb < 6; nb++) {
                mma_tf32(d[0][nb][0], d[0][nb][1], d[0][nb][2], d[0][nb][3],
                         a00, a01, a02, a03,
                         __float_as_uint(bf[nb].x), __float_as_uint(bf[nb].y));
                mma_tf32(d[1][nb][0], d[1][nb][1], d[1][nb][2], d[1][nb][3],
                         a10, a11, a12, a13,
                         __float_as_uint(bf[nb].x), __float_as_uint(bf[nb].y));
            }
        }
    }

    #pragma unroll
    for (int f = 0; f < 2; f++) {
        #pragma unroll
        for (int h = 0; h < 2; h++) {
            const int row = M0 + mw * 32 + f * 16 + gID + 8 * h;
            #pragma unroll
            for (int nb = 0; nb < 6; nb++) {
                const int colp = nw * 48 + nb * 8 + tig * 2;
                float2 o;
                o.x = d[f][nb][h * 2 + 0] + __ldg(&b2[colp]);
                o.y = d[f][nb][h * 2 + 1] + __ldg(&b2[colp + 1]);
                *(float2*)&out[row * 96 + colp] = o;
            }
        }
    }
}

// ---------------------------------------------------------------------------
extern "C" void kernel_launch(void* const* d_in, const int* in_sizes, int n_in,
                              void* d_out, int out_size) {
    const float* x  = (const float*)d_in[0];
    const float* w1 = (const float*)d_in[1];
    const float* b1 = (const float*)d_in[2];
    const float* w2 = (const float*)d_in[3];
    const float* b2 = (const float*)d_in[4];
    float* out = (float*)d_out;

    k_prep<<<144, 256>>>(w1, w2);
    dim3 g1(SEQ * BATCH / 128, 3);
    k_qkv<<<g1, 256>>>(x, b1);
    k_attn<<<BATCH * HEADS * NWIN, 128>>>();
    k_proj<<<SEQ * BATCH / 128, 256>>>(b2, out);
}

// round 14
// speedup vs baseline: 1.8143x; 1.0530x over previous
#include <cuda_runtime.h>
#include <mma.h>
#include <math.h>

using namespace nvcuda;

#define BATCH 64
#define HW    56
#define SEQ   3136
#define EMB   96
#define HEADS 3
#define EH    32
#define WS    7
#define WS2   49
#define NWIN  64
#define N3E   288

#define SCALE 0.17677669529663687f  // 1/sqrt(32)

// Scratch (device globals)
__device__ float g_QKV[BATCH * SEQ * N3E];   // dense [row][288]
__device__ float g_O[BATCH * SEQ * EMB];
// Pre-transposed tf32 weights in MMA fragment-major layout:
__device__ float g_W1f[3 * 2 * 6 * 12 * 32 * 2];
__device__ float g_W2f[2 * 6 * 12 * 32 * 2];

__device__ __forceinline__ void mma_tf32(float& d0, float& d1, float& d2, float& d3,
                                         unsigned a0, unsigned a1, unsigned a2, unsigned a3,
                                         unsigned b0, unsigned b1) {
    asm volatile(
        "mma.sync.aligned.m16n8k8.row.col.f32.tf32.tf32.f32 "
        "{%0,%1,%2,%3}, {%4,%5,%6,%7}, {%8,%9}, {%0,%1,%2,%3};\n"
        : "+f"(d0), "+f"(d1), "+f"(d2), "+f"(d3)
        : "r"(a0), "r"(a1), "r"(a2), "r"(a3), "r"(b0), "r"(b1));
}

__device__ __forceinline__ void cp_async16(unsigned saddr, const void* g) {
    asm volatile("cp.async.cg.shared.global [%0], [%1], 16;" :: "r"(saddr), "l"(g));
}

// ---------------------------------------------------------------------------
// K0: pre-transpose w1/w2 into tf32 fragment-major layout (tiny).
// ---------------------------------------------------------------------------
__global__ __launch_bounds__(256) void k_prep(const float* __restrict__ w1,
                                              const float* __restrict__ w2) {
    int idx = blockIdx.x * 256 + threadIdx.x;
    if (idx < 27648) {
        const int r = idx & 1;
        const int lane = (idx >> 1) & 31;
        int rest = idx >> 6;
        const int nblk = rest % 12; rest /= 12;
        const int ks = rest % 6; rest /= 6;
        const int chunk = rest & 1;
        const int ct = rest >> 1;
        const int n = ct * 96 + nblk * 8 + (lane >> 2);
        const int k = chunk * 48 + ks * 8 + r * 4 + (lane & 3);
        g_W1f[idx] = wmma::__float_to_tf32(w1[n * 96 + k]);
    } else {
        int i2 = idx - 27648;
        if (i2 < 9216) {
            const int r = i2 & 1;
            const int lane = (i2 >> 1) & 31;
            int rest = i2 >> 6;
            const int nblk = rest % 12; rest /= 12;
            const int ks = rest % 6; rest /= 6;
            const int chunk = rest & 1;
            const int n = nblk * 8 + (lane >> 2);
            const int k = chunk * 48 + ks * 8 + r * 4 + (lane & 3);
            g_W2f[i2] = wmma::__float_to_tf32(w2[n * 96 + k]);
        }
    }
}

// ---------------------------------------------------------------------------
// K1: qkv = x @ w1^T + b1 via mma.sync tf32.
// Block = 128 rows x ALL 288 cols: A (x-tile) staged ONCE for both K-chunks
// via cp.async (raw fp32, tf32 HW-truncation), reused across ct=0..2.
// Smem layout [chunk(2)][slot(4)][F(48)*32 + rot(lane)] with lane rotation
// (lane + 8*slot)&31 -> conflict-free, no padding, exactly 48KB.
// ---------------------------------------------------------------------------
__global__ __launch_bounds__(256) void k_qkv(const float* __restrict__ x,
                                             const float* __restrict__ b1) {
    __shared__ __align__(16) float Asl[12288];   // 48KB exact

    const int M0 = blockIdx.x * 128;
    const int t = threadIdx.x;
    const int lane = t & 31;
    const int w = t >> 5;
    const int mw = w >> 1;
    const int nw = w & 1;
    const int gID = lane >> 2;
    const int tig = lane & 3;

    // Staging map: thread (rA = t>>1, e = t&1)
    const int rA = t >> 1, e = t & 1;
    const int gA = rA >> 4, rrA = rA & 15;
    const int slotA = (rrA >> 3) + 2 * e;
    const int Lb = (rrA & 7) * 4;
    const int rot = (Lb + 8 * slotA) & 31;
    const int Fb = gA * 6;

    // Prefetch BOTH chunks of A (12 x cp.async16 per thread)
    #pragma unroll
    for (int chunk = 0; chunk < 2; chunk++) {
        const float* xrow = &x[(M0 + rA) * 96 + chunk * 48 + 4 * e];
        unsigned sbase = (unsigned)__cvta_generic_to_shared(
            &Asl[chunk * 6144 + slotA * 1536 + rot]);
        #pragma unroll
        for (int j = 0; j < 6; j++)
            cp_async16(sbase + (unsigned)((Fb + j) * 128), &xrow[8 * j]);
    }
    asm volatile("cp.async.commit_group;");
    asm volatile("cp.async.wait_all;" ::: "memory");
    __syncthreads();

    // Per-slot read rotations
    const int rl0 = lane;
    const int rl1 = (lane + 8) & 31;
    const int rl2 = (lane + 16) & 31;
    const int rl3 = (lane + 24) & 31;

    const float2* WfB = (const float2*)g_W1f;

    for (int ct = 0; ct < 3; ct++) {
        float d[2][6][4];
        #pragma unroll
        for (int f = 0; f < 2; f++)
            #pragma unroll
            for (int nb = 0; nb < 6; nb++)
                #pragma unroll
                for (int c = 0; c < 4; c++) d[f][nb][c] = 0.f;

        #pragma unroll
        for (int chunk = 0; chunk < 2; chunk++) {
            const float* Ab = &Asl[chunk * 6144];
            const float2* Wc = WfB + ((size_t)(ct * 2 + chunk)) * 2304 + (nw * 6) * 32 + lane;
            #pragma unroll
            for (int ks = 0; ks < 6; ks++) {
                const int F0 = ((mw * 2 + 0) * 6 + ks) * 32;
                const int F1 = ((mw * 2 + 1) * 6 + ks) * 32;
                const unsigned a00 = __float_as_uint(Ab[0 * 1536 + F0 + rl0]);
                const unsigned a01 = __float_as_uint(Ab[1 * 1536 + F0 + rl1]);
                const unsigned a02 = __float_as_uint(Ab[2 * 1536 + F0 + rl2]);
                const unsigned a03 = __float_as_uint(Ab[3 * 1536 + F0 + rl3]);
                const unsigned a10 = __float_as_uint(Ab[0 * 1536 + F1 + rl0]);
                const unsigned a11 = __float_as_uint(Ab[1 * 1536 + F1 + rl1]);
                const unsigned a12 = __float_as_uint(Ab[2 * 1536 + F1 + rl2]);
                const unsigned a13 = __float_as_uint(Ab[3 * 1536 + F1 + rl3]);
                float2 bf[6];
                #pragma unroll
                for (int nb = 0; nb < 6; nb++)
                    bf[nb] = __ldg(&Wc[(ks * 12 + nb) * 32]);
                #pragma unroll
                for (int nb = 0; nb < 6; nb++) {
                    mma_tf32(d[0][nb][0], d[0][nb][1], d[0][nb][2], d[0][nb][3],
                             a00, a01, a02, a03,
                             __float_as_uint(bf[nb].x), __float_as_uint(bf[nb].y));
                    mma_tf32(d[1][nb][0], d[1][nb][1], d[1][nb][2], d[1][nb][3],
                             a10, a11, a12, a13,
                             __float_as_uint(bf[nb].x), __float_as_uint(bf[nb].y));
                }
            }
        }

        // Epilogue for this ct: dense float2 stores
        const int c0 = ct * 96;
        #pragma unroll
        for (int f = 0; f < 2; f++) {
            #pragma unroll
            for (int h = 0; h < 2; h++) {
                const int row = M0 + mw * 32 + f * 16 + gID + 8 * h;
                #pragma unroll
                for (int nb = 0; nb < 6; nb++) {
                    const int colp = nw * 48 + nb * 8 + tig * 2;
                    float2 o;
                    o.x = d[f][nb][h * 2 + 0] + __ldg(&b1[c0 + colp]);
                    o.y = d[f][nb][h * 2 + 1] + __ldg(&b1[c0 + colp + 1]);
                    *(float2*)&g_QKV[row * N3E + c0 + colp] = o;
                }
            }
        }
    }
}

// ---------------------------------------------------------------------------
// K2: window attention via raw mma.sync m16n8k8 tf32 (unchanged from R13).
// ---------------------------------------------------------------------------
__global__ __launch_bounds__(128) void k_attn() {
    __shared__ __align__(16) float sm[3 * 64 * 36];
    __shared__ int sRow[WS2];
    __shared__ int oRow[WS2];
    float (*Qs)[36] = (float(*)[36])sm;
    float (*Ks)[36] = (float(*)[36])(sm + 2304);
    float (*Vs)[36] = (float(*)[36])(sm + 4608);

    const int blk = blockIdx.x;
    const int win = blk & 63;
    const int head = (blk >> 6) % 3;
    const int b = blk / (NWIN * HEADS);
    const int t = threadIdx.x;
    const int w = t >> 5, lane = t & 31;
    const int gID = lane >> 2, tig = lane & 3;
    const int m0 = w * 16;
    const int wh = win >> 3, ww = win & 7;

    if (t < WS2) {
        const int m1 = t / 7, m2 = t % 7;
        {
            const int y  = (wh * WS + m1 + 4) % HW;
            const int xx = (ww * WS + m2 + 4) % HW;
            sRow[t] = (b * SEQ + y * HW + xx) * N3E + head * 96;
        }
        {
            const int y  = (wh * WS + m1 + 3) % HW;
            const int xx = (ww * WS + m2 + 3) % HW;
            oRow[t] = (b * SEQ + y * HW + xx) * EMB + head * EH;
        }
    }
    __syncthreads();

    for (int i = t; i < 64 * EH; i += 128) {
        const int m = i >> 5, k = i & 31;
        float q = 0.f, kk = 0.f, vv = 0.f;
        if (m < WS2) {
            const int a = sRow[m] + k * 3;
            q  = g_QKV[a]     * SCALE;
            kk = g_QKV[a + 1];
            vv = g_QKV[a + 2];
        }
        Qs[m][k] = wmma::__float_to_tf32(q);
        Ks[m][k] = wmma::__float_to_tf32(kk);
        Vs[m][k] = wmma::__float_to_tf32(vv);
    }
    __syncthreads();

    float c[8][4];
    #pragma unroll
    for (int nb = 0; nb < 8; nb++)
        #pragma unroll
        for (int q = 0; q < 4; q++) c[nb][q] = 0.f;

    #pragma unroll
    for (int ks = 0; ks < 4; ks++) {
        const float* qb = &Qs[m0 + gID][ks * 8 + tig];
        const unsigned a0 = __float_as_uint(qb[0]);
        const unsigned a1 = __float_as_uint(qb[8 * 36]);
        const unsigned a2 = __float_as_uint(qb[4]);
        const unsigned a3 = __float_as_uint(qb[8 * 36 + 4]);
        #pragma unroll
        for (int nb = 0; nb < 8; nb++) {
            const float* kbp = &Ks[nb * 8 + gID][ks * 8 + tig];
            mma_tf32(c[nb][0], c[nb][1], c[nb][2], c[nb][3],
                     a0, a1, a2, a3,
                     __float_as_uint(kbp[0]), __float_as_uint(kbp[4]));
        }
    }

    const bool lastRow = (wh == 7);
    const bool lastCol = (ww == 7);
    const int r0 = m0 + gID;
    const int r1 = r0 + 8;
    const bool rD0 = (r0 >= 28), rM0 = (r0 % 7) >= 4;
    const bool rD1 = (r1 >= 28), rM1 = (r1 % 7) >= 4;

    float mx0 = -1e30f, mx1 = -1e30f;
    #pragma unroll
    for (int nb = 0; nb < 8; nb++) {
        #pragma unroll
        for (int bc = 0; bc < 2; bc++) {
            const int col = nb * 8 + 2 * tig + bc;
            const bool cOK = (col < WS2);
            const bool cD = (col >= 28);
            const bool cM = (col % 7) >= 4;
            const bool bad0 = !cOK || (lastRow && (rD0 != cD)) || (lastCol && (rM0 != cM));
            const bool bad1 = !cOK || (lastRow && (rD1 != cD)) || (lastCol && (rM1 != cM));
            if (bad0) c[nb][bc]     = -1e30f;
            if (bad1) c[nb][2 + bc] = -1e30f;
            mx0 = fmaxf(mx0, c[nb][bc]);
            mx1 = fmaxf(mx1, c[nb][2 + bc]);
        }
    }
    mx0 = fmaxf(mx0, __shfl_xor_sync(0xffffffff, mx0, 1));
    mx0 = fmaxf(mx0, __shfl_xor_sync(0xffffffff, mx0, 2));
    mx1 = fmaxf(mx1, __shfl_xor_sync(0xffffffff, mx1, 1));
    mx1 = fmaxf(mx1, __shfl_xor_sync(0xffffffff, mx1, 2));

    float s0 = 0.f, s1 = 0.f;
    #pragma unroll
    for (int nb = 0; nb < 8; nb++) {
        #pragma unroll
        for (int bc = 0; bc < 2; bc++) {
            c[nb][bc]     = __expf(c[nb][bc] - mx0);     s0 += c[nb][bc];
            c[nb][2 + bc] = __expf(c[nb][2 + bc] - mx1); s1 += c[nb][2 + bc];
        }
    }
    s0 += __shfl_xor_sync(0xffffffff, s0, 1);
    s0 += __shfl_xor_sync(0xffffffff, s0, 2);
    s1 += __shfl_xor_sync(0xffffffff, s1, 1);
    s1 += __shfl_xor_sync(0xffffffff, s1, 2);
    const float inv0 = __frcp_rn(s0);
    const float inv1 = __frcp_rn(s1);
    #pragma unroll
    for (int nb = 0; nb < 8; nb++) {
        c[nb][0] = wmma::__float_to_tf32(c[nb][0] * inv0);
        c[nb][1] = wmma::__float_to_tf32(c[nb][1] * inv0);
        c[nb][2] = wmma::__float_to_tf32(c[nb][2] * inv1);
        c[nb][3] = wmma::__float_to_tf32(c[nb][3] * inv1);
    }

    __syncthreads();

    float* Pw = sm + w * 1088;
    #pragma unroll
    for (int nb = 0; nb < 8; nb++) {
        *(float2*)&Pw[gID * 68 + nb * 8 + 2 * tig]       = make_float2(c[nb][0], c[nb][1]);
        *(float2*)&Pw[(gID + 8) * 68 + nb * 8 + 2 * tig] = make_float2(c[nb][2], c[nb][3]);
    }
    __syncwarp();

    float o[4][4];
    #pragma unroll
    for (int nb = 0; nb < 4; nb++)
        #pragma unroll
        for (int q = 0; q < 4; q++) o[nb][q] = 0.f;

    #pragma unroll
    for (int kb = 0; kb < 8; kb++) {
        const float* pb = &Pw[gID * 68 + kb * 8 + tig];
        const unsigned a0 = __float_as_uint(pb[0]);
        const unsigned a1 = __float_as_uint(pb[8 * 68]);
        const unsigned a2 = __float_as_uint(pb[4]);
        const unsigned a3 = __float_as_uint(pb[8 * 68 + 4]);
        #pragma unroll
        for (int nb = 0; nb < 4; nb++) {
            const float* vbp = &Vs[kb * 8 + tig][nb * 8 + gID];
            mma_tf32(o[nb][0], o[nb][1], o[nb][2], o[nb][3],
                     a0, a1, a2, a3,
                     __float_as_uint(vbp[0]), __float_as_uint(vbp[4 * 36]));
        }
    }

    if (r0 < WS2) {
        const int base = oRow[r0];
        #pragma unroll
        for (int nb = 0; nb < 4; nb++)
            *(float2*)&g_O[base + nb * 8 + 2 * tig] = make_float2(o[nb][0], o[nb][1]);
    }
    if (r1 < WS2) {
        const int base = oRow[r1];
        #pragma unroll
        for (int nb = 0; nb < 4; nb++)
            *(float2*)&g_O[base + nb * 8 + 2 * tig] = make_float2(o[nb][2], o[nb][3]);
    }
}

// ---------------------------------------------------------------------------
// K3: out = O @ w2^T + b2. cp.async staging of both chunks upfront (48KB),
// lane-rotated layout, raw-fp32 A (HW tf32 truncation). Dense write.
// ---------------------------------------------------------------------------
__global__ __launch_bounds__(256) void k_proj(const float* __restrict__ b2,
                                              float* __restrict__ out) {
    __shared__ __align__(16) float Asl[12288];

    const int M0 = blockIdx.x * 128;
    const int t = threadIdx.x;
    const int lane = t & 31;
    const int w = t >> 5;
    const int mw = w >> 1;
    const int nw = w & 1;
    const int gID = lane >> 2;
    const int tig = lane & 3;

    const int rA = t >> 1, e = t & 1;
    const int gA = rA >> 4, rrA = rA & 15;
    const int slotA = (rrA >> 3) + 2 * e;
    const int Lb = (rrA & 7) * 4;
    const int rot = (Lb + 8 * slotA) & 31;
    const int Fb = gA * 6;

    #pragma unroll
    for (int chunk = 0; chunk < 2; chunk++) {
        const float* orow = &g_O[(M0 + rA) * 96 + chunk * 48 + 4 * e];
        unsigned sbase = (unsigned)__cvta_generic_to_shared(
            &Asl[chunk * 6144 + slotA * 1536 + rot]);
        #pragma unroll
        for (int j = 0; j < 6; j++)
            cp_async16(sbase + (unsigned)((Fb + j) * 128), &orow[8 * j]);
    }
    asm volatile("cp.async.commit_group;");
    asm volatile("cp.async.wait_all;" ::: "memory");
    __syncthreads();

    const int rl0 = lane;
    const int rl1 = (lane + 8) & 31;
    const int rl2 = (lane + 16) & 31;
    const int rl3 = (lane + 24) & 31;

    const float2* WfB = (const float2*)g_W2f;

    float d[2][6][4];
    #pragma unroll
    for (int f = 0; f < 2; f++)
        #pragma unroll
        for (int nb = 0; nb < 6; nb++)
            #pragma unroll
            for (int c = 0; c < 4; c++) d[f][nb][c] = 0.f;

    #pragma unroll
    for (int chunk = 0; chunk < 2; chunk++) {
        const float* Ab = &Asl[chunk * 6144];
        const float2* Wc = WfB + ((size_t)chunk) * 2304 + (nw * 6) * 32 + lane;
        #pragma unroll
        for (int ks = 0; ks < 6; ks++) {
            const int F0 = ((mw * 2 + 0) * 6 + ks) * 32;
            const int F1 = ((mw * 2 + 1) * 6 + ks) * 32;
            const unsigned a00 = __float_as_uint(Ab[0 * 1536 + F0 + rl0]);
            const unsigned a01 = __float_as_uint(Ab[1 * 1536 + F0 + rl1]);
            const unsigned a02 = __float_as_uint(Ab[2 * 1536 + F0 + rl2]);
            const unsigned a03 = __float_as_uint(Ab[3 * 1536 + F0 + rl3]);
            const unsigned a10 = __float_as_uint(Ab[0 * 1536 + F1 + rl0]);
            const unsigned a11 = __float_as_uint(Ab[1 * 1536 + F1 + rl1]);
            const unsigned a12 = __float_as_uint(Ab[2 * 1536 + F1 + rl2]);
            const unsigned a13 = __float_as_uint(Ab[3 * 1536 + F1 + rl3]);
            float2 bf[6];
            #pragma unroll
            for (int nb = 0; nb < 6; nb++)
                bf[nb] = __ldg(&Wc[(ks * 12 + nb) * 32]);
            #pragma unroll
            for (int nb = 0; nb < 6; nb++) {
                mma_tf32(d[0][nb][0], d[0][nb][1], d[0][nb][2], d[0][nb][3],
                         a00, a01, a02, a03,
                         __float_as_uint(bf[nb].x), __float_as_uint(bf[nb].y));
                mma_tf32(d[1][nb][0], d[1][nb][1], d[1][nb][2], d[1][nb][3],
                         a10, a11, a12, a13,
                         __float_as_uint(bf[nb].x), __float_as_uint(bf[nb].y));
            }
        }
    }

    #pragma unroll
    for (int f = 0; f < 2; f++) {
        #pragma unroll
        for (int h = 0; h < 2; h++) {
            const int row = M0 + mw * 32 + f * 16 + gID + 8 * h;
            #pragma unroll
            for (int nb = 0; nb < 6; nb++) {
                const int colp = nw * 48 + nb * 8 + tig * 2;
                float2 o;
                o.x = d[f][nb][h * 2 + 0] + __ldg(&b2[colp]);
                o.y = d[f][nb][h * 2 + 1] + __ldg(&b2[colp + 1]);
                *(float2*)&out[row * 96 + colp] = o;
            }
        }
    }
}

// ---------------------------------------------------------------------------
extern "C" void kernel_launch(void* const* d_in, const int* in_sizes, int n_in,
                              void* d_out, int out_size) {
    const float* x  = (const float*)d_in[0];
    const float* w1 = (const float*)d_in[1];
    const float* b1 = (const float*)d_in[2];
    const float* w2 = (const float*)d_in[3];
    const float* b2 = (const float*)d_in[4];
    float* out = (float*)d_out;

    k_prep<<<144, 256>>>(w1, w2);
    k_qkv<<<SEQ * BATCH / 128, 256>>>(x, b1);
    k_attn<<<BATCH * HEADS * NWIN, 128>>>();
    k_proj<<<SEQ * BATCH / 128, 256>>>(b2, out);
}

// round 15
// speedup vs baseline: 1.9047x; 1.0498x over previous
#include <cuda_runtime.h>
#include <cuda_fp16.h>
#include <mma.h>
#include <math.h>

using namespace nvcuda;

#define BATCH 64
#define HW    56
#define SEQ   3136
#define EMB   96
#define HEADS 3
#define EH    32
#define WS    7
#define WS2   49
#define NWIN  64
#define N3E   288

#define SCALE 0.17677669529663687f  // 1/sqrt(32)

// Scratch (device globals)
__device__ __half g_QKV[BATCH * SEQ * N3E];  // fp16 dense [row][288]
__device__ float  g_O[BATCH * SEQ * EMB];
// Pre-transposed tf32 weights in MMA fragment-major layout:
__device__ float g_W1f[3 * 2 * 6 * 12 * 32 * 2];
__device__ float g_W2f[2 * 6 * 12 * 32 * 2];

__device__ __forceinline__ void mma_tf32(float& d0, float& d1, float& d2, float& d3,
                                         unsigned a0, unsigned a1, unsigned a2, unsigned a3,
                                         unsigned b0, unsigned b1) {
    asm volatile(
        "mma.sync.aligned.m16n8k8.row.col.f32.tf32.tf32.f32 "
        "{%0,%1,%2,%3}, {%4,%5,%6,%7}, {%8,%9}, {%0,%1,%2,%3};\n"
        : "+f"(d0), "+f"(d1), "+f"(d2), "+f"(d3)
        : "r"(a0), "r"(a1), "r"(a2), "r"(a3), "r"(b0), "r"(b1));
}

__device__ __forceinline__ void cp_async16(unsigned saddr, const void* g) {
    asm volatile("cp.async.cg.shared.global [%0], [%1], 16;" :: "r"(saddr), "l"(g));
}

// ---------------------------------------------------------------------------
// K0: pre-transpose w1/w2 into tf32 fragment-major layout (tiny).
// ---------------------------------------------------------------------------
__global__ __launch_bounds__(256) void k_prep(const float* __restrict__ w1,
                                              const float* __restrict__ w2) {
    int idx = blockIdx.x * 256 + threadIdx.x;
    if (idx < 27648) {
        const int r = idx & 1;
        const int lane = (idx >> 1) & 31;
        int rest = idx >> 6;
        const int nblk = rest % 12; rest /= 12;
        const int ks = rest % 6; rest /= 6;
        const int chunk = rest & 1;
        const int ct = rest >> 1;
        const int n = ct * 96 + nblk * 8 + (lane >> 2);
        const int k = chunk * 48 + ks * 8 + r * 4 + (lane & 3);
        g_W1f[idx] = wmma::__float_to_tf32(w1[n * 96 + k]);
    } else {
        int i2 = idx - 27648;
        if (i2 < 9216) {
            const int r = i2 & 1;
            const int lane = (i2 >> 1) & 31;
            int rest = i2 >> 6;
            const int nblk = rest % 12; rest /= 12;
            const int ks = rest % 6; rest /= 6;
            const int chunk = rest & 1;
            const int n = nblk * 8 + (lane >> 2);
            const int k = chunk * 48 + ks * 8 + r * 4 + (lane & 3);
            g_W2f[i2] = wmma::__float_to_tf32(w2[n * 96 + k]);
        }
    }
}

// ---------------------------------------------------------------------------
// K1: qkv = x @ w1^T + b1 via mma.sync tf32. A staged once via cp.async,
// reused across ct=0..2. Output stored as fp16 (half2, rounded) -> halves
// qkv store traffic.
// ---------------------------------------------------------------------------
__global__ __launch_bounds__(256) void k_qkv(const float* __restrict__ x,
                                             const float* __restrict__ b1) {
    __shared__ __align__(16) float Asl[12288];   // 48KB exact

    const int M0 = blockIdx.x * 128;
    const int t = threadIdx.x;
    const int lane = t & 31;
    const int w = t >> 5;
    const int mw = w >> 1;
    const int nw = w & 1;
    const int gID = lane >> 2;
    const int tig = lane & 3;

    const int rA = t >> 1, e = t & 1;
    const int gA = rA >> 4, rrA = rA & 15;
    const int slotA = (rrA >> 3) + 2 * e;
    const int Lb = (rrA & 7) * 4;
    const int rot = (Lb + 8 * slotA) & 31;
    const int Fb = gA * 6;

    #pragma unroll
    for (int chunk = 0; chunk < 2; chunk++) {
        const float* xrow = &x[(M0 + rA) * 96 + chunk * 48 + 4 * e];
        unsigned sbase = (unsigned)__cvta_generic_to_shared(
            &Asl[chunk * 6144 + slotA * 1536 + rot]);
        #pragma unroll
        for (int j = 0; j < 6; j++)
            cp_async16(sbase + (unsigned)((Fb + j) * 128), &xrow[8 * j]);
    }
    asm volatile("cp.async.commit_group;");
    asm volatile("cp.async.wait_all;" ::: "memory");
    __syncthreads();

    const int rl0 = lane;
    const int rl1 = (lane + 8) & 31;
    const int rl2 = (lane + 16) & 31;
    const int rl3 = (lane + 24) & 31;

    const float2* WfB = (const float2*)g_W1f;

    for (int ct = 0; ct < 3; ct++) {
        float d[2][6][4];
        #pragma unroll
        for (int f = 0; f < 2; f++)
            #pragma unroll
            for (int nb = 0; nb < 6; nb++)
                #pragma unroll
                for (int c = 0; c < 4; c++) d[f][nb][c] = 0.f;

        #pragma unroll
        for (int chunk = 0; chunk < 2; chunk++) {
            const float* Ab = &Asl[chunk * 6144];
            const float2* Wc = WfB + ((size_t)(ct * 2 + chunk)) * 2304 + (nw * 6) * 32 + lane;
            #pragma unroll
            for (int ks = 0; ks < 6; ks++) {
                const int F0 = ((mw * 2 + 0) * 6 + ks) * 32;
                const int F1 = ((mw * 2 + 1) * 6 + ks) * 32;
                const unsigned a00 = __float_as_uint(Ab[0 * 1536 + F0 + rl0]);
                const unsigned a01 = __float_as_uint(Ab[1 * 1536 + F0 + rl1]);
                const unsigned a02 = __float_as_uint(Ab[2 * 1536 + F0 + rl2]);
                const unsigned a03 = __float_as_uint(Ab[3 * 1536 + F0 + rl3]);
                const unsigned a10 = __float_as_uint(Ab[0 * 1536 + F1 + rl0]);
                const unsigned a11 = __float_as_uint(Ab[1 * 1536 + F1 + rl1]);
                const unsigned a12 = __float_as_uint(Ab[2 * 1536 + F1 + rl2]);
                const unsigned a13 = __float_as_uint(Ab[3 * 1536 + F1 + rl3]);
                float2 bf[6];
                #pragma unroll
                for (int nb = 0; nb < 6; nb++)
                    bf[nb] = __ldg(&Wc[(ks * 12 + nb) * 32]);
                #pragma unroll
                for (int nb = 0; nb < 6; nb++) {
                    mma_tf32(d[0][nb][0], d[0][nb][1], d[0][nb][2], d[0][nb][3],
                             a00, a01, a02, a03,
                             __float_as_uint(bf[nb].x), __float_as_uint(bf[nb].y));
                    mma_tf32(d[1][nb][0], d[1][nb][1], d[1][nb][2], d[1][nb][3],
                             a10, a11, a12, a13,
                             __float_as_uint(bf[nb].x), __float_as_uint(bf[nb].y));
                }
            }
        }

        // Epilogue: bias + fp16 rounding + half2 stores (coalesced)
        const int c0 = ct * 96;
        #pragma unroll
        for (int f = 0; f < 2; f++) {
            #pragma unroll
            for (int h = 0; h < 2; h++) {
                const int row = M0 + mw * 32 + f * 16 + gID + 8 * h;
                #pragma unroll
                for (int nb = 0; nb < 6; nb++) {
                    const int colp = nw * 48 + nb * 8 + tig * 2;
                    const float ox = d[f][nb][h * 2 + 0] + __ldg(&b1[c0 + colp]);
                    const float oy = d[f][nb][h * 2 + 1] + __ldg(&b1[c0 + colp + 1]);
                    *(__half2*)&g_QKV[row * N3E + c0 + colp] = __floats2half2_rn(ox, oy);
                }
            }
        }
    }
}

// ---------------------------------------------------------------------------
// K2: window attention via raw mma.sync m16n8k8 tf32. Gathers fp16 Q/K/V
// from g_QKV (half loads, fp32 convert at staging). Otherwise unchanged.
// ---------------------------------------------------------------------------
__global__ __launch_bounds__(128) void k_attn() {
    __shared__ __align__(16) float sm[3 * 64 * 36];
    __shared__ int sRow[WS2];
    __shared__ int oRow[WS2];
    float (*Qs)[36] = (float(*)[36])sm;
    float (*Ks)[36] = (float(*)[36])(sm + 2304);
    float (*Vs)[36] = (float(*)[36])(sm + 4608);

    const int blk = blockIdx.x;
    const int win = blk & 63;
    const int head = (blk >> 6) % 3;
    const int b = blk / (NWIN * HEADS);
    const int t = threadIdx.x;
    const int w = t >> 5, lane = t & 31;
    const int gID = lane >> 2, tig = lane & 3;
    const int m0 = w * 16;
    const int wh = win >> 3, ww = win & 7;

    if (t < WS2) {
        const int m1 = t / 7, m2 = t % 7;
        {
            const int y  = (wh * WS + m1 + 4) % HW;
            const int xx = (ww * WS + m2 + 4) % HW;
            sRow[t] = (b * SEQ + y * HW + xx) * N3E + head * 96;
        }
        {
            const int y  = (wh * WS + m1 + 3) % HW;
            const int xx = (ww * WS + m2 + 3) % HW;
            oRow[t] = (b * SEQ + y * HW + xx) * EMB + head * EH;
        }
    }
    __syncthreads();

    for (int i = t; i < 64 * EH; i += 128) {
        const int m = i >> 5, k = i & 31;
        float q = 0.f, kk = 0.f, vv = 0.f;
        if (m < WS2) {
            const int a = sRow[m] + k * 3;
            q  = __half2float(g_QKV[a])     * SCALE;
            kk = __half2float(g_QKV[a + 1]);
            vv = __half2float(g_QKV[a + 2]);
        }
        Qs[m][k] = wmma::__float_to_tf32(q);
        Ks[m][k] = wmma::__float_to_tf32(kk);
        Vs[m][k] = wmma::__float_to_tf32(vv);
    }
    __syncthreads();

    float c[8][4];
    #pragma unroll
    for (int nb = 0; nb < 8; nb++)
        #pragma unroll
        for (int q = 0; q < 4; q++) c[nb][q] = 0.f;

    #pragma unroll
    for (int ks = 0; ks < 4; ks++) {
        const float* qb = &Qs[m0 + gID][ks * 8 + tig];
        const unsigned a0 = __float_as_uint(qb[0]);
        const unsigned a1 = __float_as_uint(qb[8 * 36]);
        const unsigned a2 = __float_as_uint(qb[4]);
        const unsigned a3 = __float_as_uint(qb[8 * 36 + 4]);
        #pragma unroll
        for (int nb = 0; nb < 8; nb++) {
            const float* kbp = &Ks[nb * 8 + gID][ks * 8 + tig];
            mma_tf32(c[nb][0], c[nb][1], c[nb][2], c[nb][3],
                     a0, a1, a2, a3,
                     __float_as_uint(kbp[0]), __float_as_uint(kbp[4]));
        }
    }

    const bool lastRow = (wh == 7);
    const bool lastCol = (ww == 7);
    const int r0 = m0 + gID;
    const int r1 = r0 + 8;
    const bool rD0 = (r0 >= 28), rM0 = (r0 % 7) >= 4;
    const bool rD1 = (r1 >= 28), rM1 = (r1 % 7) >= 4;

    float mx0 = -1e30f, mx1 = -1e30f;
    #pragma unroll
    for (int nb = 0; nb < 8; nb++) {
        #pragma unroll
        for (int bc = 0; bc < 2; bc++) {
            const int col = nb * 8 + 2 * tig + bc;
            const bool cOK = (col < WS2);
            const bool cD = (col >= 28);
            const bool cM = (col % 7) >= 4;
            const bool bad0 = !cOK || (lastRow && (rD0 != cD)) || (lastCol && (rM0 != cM));
            const bool bad1 = !cOK || (lastRow && (rD1 != cD)) || (lastCol && (rM1 != cM));
            if (bad0) c[nb][bc]     = -1e30f;
            if (bad1) c[nb][2 + bc] = -1e30f;
            mx0 = fmaxf(mx0, c[nb][bc]);
            mx1 = fmaxf(mx1, c[nb][2 + bc]);
        }
    }
    mx0 = fmaxf(mx0, __shfl_xor_sync(0xffffffff, mx0, 1));
    mx0 = fmaxf(mx0, __shfl_xor_sync(0xffffffff, mx0, 2));
    mx1 = fmaxf(mx1, __shfl_xor_sync(0xffffffff, mx1, 1));
    mx1 = fmaxf(mx1, __shfl_xor_sync(0xffffffff, mx1, 2));

    float s0 = 0.f, s1 = 0.f;
    #pragma unroll
    for (int nb = 0; nb < 8; nb++) {
        #pragma unroll
        for (int bc = 0; bc < 2; bc++) {
            c[nb][bc]     = __expf(c[nb][bc] - mx0);     s0 += c[nb][bc];
            c[nb][2 + bc] = __expf(c[nb][2 + bc] - mx1); s1 += c[nb][2 + bc];
        }
    }
    s0 += __shfl_xor_sync(0xffffffff, s0, 1);
    s0 += __shfl_xor_sync(0xffffffff, s0, 2);
    s1 += __shfl_xor_sync(0xffffffff, s1, 1);
    s1 += __shfl_xor_sync(0xffffffff, s1, 2);
    const float inv0 = __frcp_rn(s0);
    const float inv1 = __frcp_rn(s1);
    #pragma unroll
    for (int nb = 0; nb < 8; nb++) {
        c[nb][0] = wmma::__float_to_tf32(c[nb][0] * inv0);
        c[nb][1] = wmma::__float_to_tf32(c[nb][1] * inv0);
        c[nb][2] = wmma::__float_to_tf32(c[nb][2] * inv1);
        c[nb][3] = wmma::__float_to_tf32(c[nb][3] * inv1);
    }

    __syncthreads();

    float* Pw = sm + w * 1088;
    #pragma unroll
    for (int nb = 0; nb < 8; nb++) {
        *(float2*)&Pw[gID * 68 + nb * 8 + 2 * tig]       = make_float2(c[nb][0], c[nb][1]);
        *(float2*)&Pw[(gID + 8) * 68 + nb * 8 + 2 * tig] = make_float2(c[nb][2], c[nb][3]);
    }
    __syncwarp();

    float o[4][4];
    #pragma unroll
    for (int nb = 0; nb < 4; nb++)
        #pragma unroll
        for (int q = 0; q < 4; q++) o[nb][q] = 0.f;

    #pragma unroll
    for (int kb = 0; kb < 8; kb++) {
        const float* pb = &Pw[gID * 68 + kb * 8 + tig];
        const unsigned a0 = __float_as_uint(pb[0]);
        const unsigned a1 = __float_as_uint(pb[8 * 68]);
        const unsigned a2 = __float_as_uint(pb[4]);
        const unsigned a3 = __float_as_uint(pb[8 * 68 + 4]);
        #pragma unroll
        for (int nb = 0; nb < 4; nb++) {
            const float* vbp = &Vs[kb * 8 + tig][nb * 8 + gID];
            mma_tf32(o[nb][0], o[nb][1], o[nb][2], o[nb][3],
                     a0, a1, a2, a3,
                     __float_as_uint(vbp[0]), __float_as_uint(vbp[4 * 36]));
        }
    }

    if (r0 < WS2) {
        const int base = oRow[r0];
        #pragma unroll
        for (int nb = 0; nb < 4; nb++)
            *(float2*)&g_O[base + nb * 8 + 2 * tig] = make_float2(o[nb][0], o[nb][1]);
    }
    if (r1 < WS2) {
        const int base = oRow[r1];
        #pragma unroll
        for (int nb = 0; nb < 4; nb++)
            *(float2*)&g_O[base + nb * 8 + 2 * tig] = make_float2(o[nb][2], o[nb][3]);
    }
}

// ---------------------------------------------------------------------------
// K3: out = O @ w2^T + b2 (unchanged from R14).
// ---------------------------------------------------------------------------
__global__ __launch_bounds__(256) void k_proj(const float* __restrict__ b2,
                                              float* __restrict__ out) {
    __shared__ __align__(16) float Asl[12288];

    const int M0 = blockIdx.x * 128;
    const int t = threadIdx.x;
    const int lane = t & 31;
    const int w = t >> 5;
    const int mw = w >> 1;
    const int nw = w & 1;
    const int gID = lane >> 2;
    const int tig = lane & 3;

    const int rA = t >> 1, e = t & 1;
    const int gA = rA >> 4, rrA = rA & 15;
    const int slotA = (rrA >> 3) + 2 * e;
    const int Lb = (rrA & 7) * 4;
    const int rot = (Lb + 8 * slotA) & 31;
    const int Fb = gA * 6;

    #pragma unroll
    for (int chunk = 0; chunk < 2; chunk++) {
        const float* orow = &g_O[(M0 + rA) * 96 + chunk * 48 + 4 * e];
        unsigned sbase = (unsigned)__cvta_generic_to_shared(
            &Asl[chunk * 6144 + slotA * 1536 + rot]);
        #pragma unroll
        for (int j = 0; j < 6; j++)
            cp_async16(sbase + (unsigned)((Fb + j) * 128), &orow[8 * j]);
    }
    asm volatile("cp.async.commit_group;");
    asm volatile("cp.async.wait_all;" ::: "memory");
    __syncthreads();

    const int rl0 = lane;
    const int rl1 = (lane + 8) & 31;
    const int rl2 = (lane + 16) & 31;
    const int rl3 = (lane + 24) & 31;

    const float2* WfB = (const float2*)g_W2f;

    float d[2][6][4];
    #pragma unroll
    for (int f = 0; f < 2; f++)
        #pragma unroll
        for (int nb = 0; nb < 6; nb++)
            #pragma unroll
            for (int c = 0; c < 4; c++) d[f][nb][c] = 0.f;

    #pragma unroll
    for (int chunk = 0; chunk < 2; chunk++) {
        const float* Ab = &Asl[chunk * 6144];
        const float2* Wc = WfB + ((size_t)chunk) * 2304 + (nw * 6) * 32 + lane;
        #pragma unroll
        for (int ks = 0; ks < 6; ks++) {
            const int F0 = ((mw * 2 + 0) * 6 + ks) * 32;
            const int F1 = ((mw * 2 + 1) * 6 + ks) * 32;
            const unsigned a00 = __float_as_uint(Ab[0 * 1536 + F0 + rl0]);
            const unsigned a01 = __float_as_uint(Ab[1 * 1536 + F0 + rl1]);
            const unsigned a02 = __float_as_uint(Ab[2 * 1536 + F0 + rl2]);
            const unsigned a03 = __float_as_uint(Ab[3 * 1536 + F0 + rl3]);
            const unsigned a10 = __float_as_uint(Ab[0 * 1536 + F1 + rl0]);
            const unsigned a11 = __float_as_uint(Ab[1 * 1536 + F1 + rl1]);
            const unsigned a12 = __float_as_uint(Ab[2 * 1536 + F1 + rl2]);
            const unsigned a13 = __float_as_uint(Ab[3 * 1536 + F1 + rl3]);
            float2 bf[6];
            #pragma unroll
            for (int nb = 0; nb < 6; nb++)
                bf[nb] = __ldg(&Wc[(ks * 12 + nb) * 32]);
            #pragma unroll
            for (int nb = 0; nb < 6; nb++) {
                mma_tf32(d[0][nb][0], d[0][nb][1], d[0][nb][2], d[0][nb][3],
                         a00, a01, a02, a03,
                         __float_as_uint(bf[nb].x), __float_as_uint(bf[nb].y));
                mma_tf32(d[1][nb][0], d[1][nb][1], d[1][nb][2], d[1][nb][3],
                         a10, a11, a12, a13,
                         __float_as_uint(bf[nb].x), __float_as_uint(bf[nb].y));
            }
        }
    }

    #pragma unroll
    for (int f = 0; f < 2; f++) {
        #pragma unroll
        for (int h = 0; h < 2; h++) {
            const int row = M0 + mw * 32 + f * 16 + gID + 8 * h;
            #pragma unroll
            for (int nb = 0; nb < 6; nb++) {
                const int colp = nw * 48 + nb * 8 + tig * 2;
                float2 o;
                o.x = d[f][nb][h * 2 + 0] + __ldg(&b2[colp]);
                o.y = d[f][nb][h * 2 + 1] + __ldg(&b2[colp + 1]);
                *(float2*)&out[row * 96 + colp] = o;
            }
        }
    }
}

// ---------------------------------------------------------------------------
extern "C" void kernel_launch(void* const* d_in, const int* in_sizes, int n_in,
                              void* d_out, int out_size) {
    const float* x  = (const float*)d_in[0];
    const float* w1 = (const float*)d_in[1];
    const float* b1 = (const float*)d_in[2];
    const float* w2 = (const float*)d_in[3];
    const float* b2 = (const float*)d_in[4];
    float* out = (float*)d_out;

    k_prep<<<144, 256>>>(w1, w2);
    k_qkv<<<SEQ * BATCH / 128, 256>>>(x, b1);
    k_attn<<<BATCH * HEADS * NWIN, 128>>>();
    k_proj<<<SEQ * BATCH / 128, 256>>>(b2, out);
}

// round 16
// speedup vs baseline: 1.9801x; 1.0396x over previous
#include <cuda_runtime.h>
#include <cuda_fp16.h>
#include <mma.h>
#include <math.h>

using namespace nvcuda;

#define BATCH 64
#define HW    56
#define SEQ   3136
#define EMB   96
#define HEADS 3
#define EH    32
#define WS    7
#define WS2   49
#define NWIN  64
#define N3E   288

#define SCALE 0.17677669529663687f  // 1/sqrt(32)

// Scratch (device globals)
__device__ __half g_QKV[BATCH * SEQ * N3E];  // fp16 dense [row][288]
__device__ float  g_O[BATCH * SEQ * EMB];
// Pre-transposed tf32 weights in MMA fragment-major layout:
__device__ float g_W1f[3 * 2 * 6 * 12 * 32 * 2];
__device__ float g_W2f[2 * 6 * 12 * 32 * 2];

__device__ __forceinline__ void mma_tf32(float& d0, float& d1, float& d2, float& d3,
                                         unsigned a0, unsigned a1, unsigned a2, unsigned a3,
                                         unsigned b0, unsigned b1) {
    asm volatile(
        "mma.sync.aligned.m16n8k8.row.col.f32.tf32.tf32.f32 "
        "{%0,%1,%2,%3}, {%4,%5,%6,%7}, {%8,%9}, {%0,%1,%2,%3};\n"
        : "+f"(d0), "+f"(d1), "+f"(d2), "+f"(d3)
        : "r"(a0), "r"(a1), "r"(a2), "r"(a3), "r"(b0), "r"(b1));
}

__device__ __forceinline__ void cp_async16(unsigned saddr, const void* g) {
    asm volatile("cp.async.cg.shared.global [%0], [%1], 16;" :: "r"(saddr), "l"(g));
}

// ---------------------------------------------------------------------------
// K0: pre-transpose w1/w2 into tf32 fragment-major layout (tiny).
// ---------------------------------------------------------------------------
__global__ __launch_bounds__(256) void k_prep(const float* __restrict__ w1,
                                              const float* __restrict__ w2) {
    int idx = blockIdx.x * 256 + threadIdx.x;
    if (idx < 27648) {
        const int r = idx & 1;
        const int lane = (idx >> 1) & 31;
        int rest = idx >> 6;
        const int nblk = rest % 12; rest /= 12;
        const int ks = rest % 6; rest /= 6;
        const int chunk = rest & 1;
        const int ct = rest >> 1;
        const int n = ct * 96 + nblk * 8 + (lane >> 2);
        const int k = chunk * 48 + ks * 8 + r * 4 + (lane & 3);
        g_W1f[idx] = wmma::__float_to_tf32(w1[n * 96 + k]);
    } else {
        int i2 = idx - 27648;
        if (i2 < 9216) {
            const int r = i2 & 1;
            const int lane = (i2 >> 1) & 31;
            int rest = i2 >> 6;
            const int nblk = rest % 12; rest /= 12;
            const int ks = rest % 6; rest /= 6;
            const int chunk = rest & 1;
            const int n = nblk * 8 + (lane >> 2);
            const int k = chunk * 48 + ks * 8 + r * 4 + (lane & 3);
            g_W2f[i2] = wmma::__float_to_tf32(w2[n * 96 + k]);
        }
    }
}

// ---------------------------------------------------------------------------
// K1: qkv = x @ w1^T + b1 via mma.sync tf32.  64-ROW tile (24KB smem ->
// 2x blocks/SM vs R15). A staged once via cp.async, reused across ct=0..2.
// Smem [chunk(2)][slot(4)][F(24)*32 + rot(lane)], slot stride 768.
// 8 warps: mw=w>>1 -> 16 rows, nw=w&1 -> 48 cols. fp16 output.
// ---------------------------------------------------------------------------
__global__ __launch_bounds__(256) void k_qkv(const float* __restrict__ x,
                                             const float* __restrict__ b1) {
    __shared__ __align__(16) float Asl[6144];   // 24KB

    const int M0 = blockIdx.x * 64;
    const int t = threadIdx.x;
    const int lane = t & 31;
    const int w = t >> 5;
    const int mw = w >> 1;
    const int nw = w & 1;
    const int gID = lane >> 2;
    const int tig = lane & 3;

    // Staging: 4 threads per row; sub = hi (col-quarter) + jh (ks-half)
    const int rA = t >> 2, sub = t & 3;
    const int hi = sub & 1, jh = sub >> 1;
    const int gA = rA >> 4, rrA = rA & 15;
    const int slotA = (rrA >> 3) + 2 * hi;
    const int Lb = (rrA & 7) * 4;
    const int rot = (Lb + 8 * slotA) & 31;
    const int Fb = gA * 6 + jh * 3;

    #pragma unroll
    for (int chunk = 0; chunk < 2; chunk++) {
        const float* xrow = &x[(M0 + rA) * 96 + chunk * 48 + 4 * hi + 24 * jh];
        unsigned sbase = (unsigned)__cvta_generic_to_shared(
            &Asl[chunk * 3072 + slotA * 768 + rot]);
        #pragma unroll
        for (int i = 0; i < 3; i++)
            cp_async16(sbase + (unsigned)((Fb + i) * 128), &xrow[8 * i]);
    }
    asm volatile("cp.async.commit_group;");
    asm volatile("cp.async.wait_all;" ::: "memory");
    __syncthreads();

    const int rl0 = lane;
    const int rl1 = (lane + 8) & 31;
    const int rl2 = (lane + 16) & 31;
    const int rl3 = (lane + 24) & 31;

    const float2* WfB = (const float2*)g_W1f;

    for (int ct = 0; ct < 3; ct++) {
        float d[6][4];
        #pragma unroll
        for (int nb = 0; nb < 6; nb++)
            #pragma unroll
            for (int c = 0; c < 4; c++) d[nb][c] = 0.f;

        #pragma unroll
        for (int chunk = 0; chunk < 2; chunk++) {
            const float* Ab = &Asl[chunk * 3072];
            const float2* Wc = WfB + ((size_t)(ct * 2 + chunk)) * 2304 + (nw * 6) * 32 + lane;
            #pragma unroll
            for (int ks = 0; ks < 6; ks++) {
                const int F0 = (mw * 6 + ks) * 32;
                const unsigned a0 = __float_as_uint(Ab[0 * 768 + F0 + rl0]);
                const unsigned a1 = __float_as_uint(Ab[1 * 768 + F0 + rl1]);
                const unsigned a2 = __float_as_uint(Ab[2 * 768 + F0 + rl2]);
                const unsigned a3 = __float_as_uint(Ab[3 * 768 + F0 + rl3]);
                float2 bf[6];
                #pragma unroll
                for (int nb = 0; nb < 6; nb++)
                    bf[nb] = __ldg(&Wc[(ks * 12 + nb) * 32]);
                #pragma unroll
                for (int nb = 0; nb < 6; nb++)
                    mma_tf32(d[nb][0], d[nb][1], d[nb][2], d[nb][3],
                             a0, a1, a2, a3,
                             __float_as_uint(bf[nb].x), __float_as_uint(bf[nb].y));
            }
        }

        // Epilogue: bias + fp16 rounding + half2 stores (coalesced)
        const int c0 = ct * 96;
        #pragma unroll
        for (int h = 0; h < 2; h++) {
            const int row = M0 + mw * 16 + gID + 8 * h;
            #pragma unroll
            for (int nb = 0; nb < 6; nb++) {
                const int colp = nw * 48 + nb * 8 + tig * 2;
                const float ox = d[nb][h * 2 + 0] + __ldg(&b1[c0 + colp]);
                const float oy = d[nb][h * 2 + 1] + __ldg(&b1[c0 + colp + 1]);
                *(__half2*)&g_QKV[row * N3E + c0 + colp] = __floats2half2_rn(ox, oy);
            }
        }
    }
}

// ---------------------------------------------------------------------------
// K2: window attention via raw mma.sync m16n8k8 tf32 (unchanged from R15).
// ---------------------------------------------------------------------------
__global__ __launch_bounds__(128) void k_attn() {
    __shared__ __align__(16) float sm[3 * 64 * 36];
    __shared__ int sRow[WS2];
    __shared__ int oRow[WS2];
    float (*Qs)[36] = (float(*)[36])sm;
    float (*Ks)[36] = (float(*)[36])(sm + 2304);
    float (*Vs)[36] = (float(*)[36])(sm + 4608);

    const int blk = blockIdx.x;
    const int win = blk & 63;
    const int head = (blk >> 6) % 3;
    const int b = blk / (NWIN * HEADS);
    const int t = threadIdx.x;
    const int w = t >> 5, lane = t & 31;
    const int gID = lane >> 2, tig = lane & 3;
    const int m0 = w * 16;
    const int wh = win >> 3, ww = win & 7;

    if (t < WS2) {
        const int m1 = t / 7, m2 = t % 7;
        {
            const int y  = (wh * WS + m1 + 4) % HW;
            const int xx = (ww * WS + m2 + 4) % HW;
            sRow[t] = (b * SEQ + y * HW + xx) * N3E + head * 96;
        }
        {
            const int y  = (wh * WS + m1 + 3) % HW;
            const int xx = (ww * WS + m2 + 3) % HW;
            oRow[t] = (b * SEQ + y * HW + xx) * EMB + head * EH;
        }
    }
    __syncthreads();

    for (int i = t; i < 64 * EH; i += 128) {
        const int m = i >> 5, k = i & 31;
        float q = 0.f, kk = 0.f, vv = 0.f;
        if (m < WS2) {
            const int a = sRow[m] + k * 3;
            q  = __half2float(g_QKV[a])     * SCALE;
            kk = __half2float(g_QKV[a + 1]);
            vv = __half2float(g_QKV[a + 2]);
        }
        Qs[m][k] = wmma::__float_to_tf32(q);
        Ks[m][k] = wmma::__float_to_tf32(kk);
        Vs[m][k] = wmma::__float_to_tf32(vv);
    }
    __syncthreads();

    float c[8][4];
    #pragma unroll
    for (int nb = 0; nb < 8; nb++)
        #pragma unroll
        for (int q = 0; q < 4; q++) c[nb][q] = 0.f;

    #pragma unroll
    for (int ks = 0; ks < 4; ks++) {
        const float* qb = &Qs[m0 + gID][ks * 8 + tig];
        const unsigned a0 = __float_as_uint(qb[0]);
        const unsigned a1 = __float_as_uint(qb[8 * 36]);
        const unsigned a2 = __float_as_uint(qb[4]);
        const unsigned a3 = __float_as_uint(qb[8 * 36 + 4]);
        #pragma unroll
        for (int nb = 0; nb < 8; nb++) {
            const float* kbp = &Ks[nb * 8 + gID][ks * 8 + tig];
            mma_tf32(c[nb][0], c[nb][1], c[nb][2], c[nb][3],
                     a0, a1, a2, a3,
                     __float_as_uint(kbp[0]), __float_as_uint(kbp[4]));
        }
    }

    const bool lastRow = (wh == 7);
    const bool lastCol = (ww == 7);
    const int r0 = m0 + gID;
    const int r1 = r0 + 8;
    const bool rD0 = (r0 >= 28), rM0 = (r0 % 7) >= 4;
    const bool rD1 = (r1 >= 28), rM1 = (r1 % 7) >= 4;

    float mx0 = -1e30f, mx1 = -1e30f;
    #pragma unroll
    for (int nb = 0; nb < 8; nb++) {
        #pragma unroll
        for (int bc = 0; bc < 2; bc++) {
            const int col = nb * 8 + 2 * tig + bc;
            const bool cOK = (col < WS2);
            const bool cD = (col >= 28);
            const bool cM = (col % 7) >= 4;
            const bool bad0 = !cOK || (lastRow && (rD0 != cD)) || (lastCol && (rM0 != cM));
            const bool bad1 = !cOK || (lastRow && (rD1 != cD)) || (lastCol && (rM1 != cM));
            if (bad0) c[nb][bc]     = -1e30f;
            if (bad1) c[nb][2 + bc] = -1e30f;
            mx0 = fmaxf(mx0, c[nb][bc]);
            mx1 = fmaxf(mx1, c[nb][2 + bc]);
        }
    }
    mx0 = fmaxf(mx0, __shfl_xor_sync(0xffffffff, mx0, 1));
    mx0 = fmaxf(mx0, __shfl_xor_sync(0xffffffff, mx0, 2));
    mx1 = fmaxf(mx1, __shfl_xor_sync(0xffffffff, mx1, 1));
    mx1 = fmaxf(mx1, __shfl_xor_sync(0xffffffff, mx1, 2));

    float s0 = 0.f, s1 = 0.f;
    #pragma unroll
    for (int nb = 0; nb < 8; nb++) {
        #pragma unroll
        for (int bc = 0; bc < 2; bc++) {
            c[nb][bc]     = __expf(c[nb][bc] - mx0);     s0 += c[nb][bc];
            c[nb][2 + bc] = __expf(c[nb][2 + bc] - mx1); s1 += c[nb][2 + bc];
        }
    }
    s0 += __shfl_xor_sync(0xffffffff, s0, 1);
    s0 += __shfl_xor_sync(0xffffffff, s0, 2);
    s1 += __shfl_xor_sync(0xffffffff, s1, 1);
    s1 += __shfl_xor_sync(0xffffffff, s1, 2);
    const float inv0 = __frcp_rn(s0);
    const float inv1 = __frcp_rn(s1);
    #pragma unroll
    for (int nb = 0; nb < 8; nb++) {
        c[nb][0] = wmma::__float_to_tf32(c[nb][0] * inv0);
        c[nb][1] = wmma::__float_to_tf32(c[nb][1] * inv0);
        c[nb][2] = wmma::__float_to_tf32(c[nb][2] * inv1);
        c[nb][3] = wmma::__float_to_tf32(c[nb][3] * inv1);
    }

    __syncthreads();

    float* Pw = sm + w * 1088;
    #pragma unroll
    for (int nb = 0; nb < 8; nb++) {
        *(float2*)&Pw[gID * 68 + nb * 8 + 2 * tig]       = make_float2(c[nb][0], c[nb][1]);
        *(float2*)&Pw[(gID + 8) * 68 + nb * 8 + 2 * tig] = make_float2(c[nb][2], c[nb][3]);
    }
    __syncwarp();

    float o[4][4];
    #pragma unroll
    for (int nb = 0; nb < 4; nb++)
        #pragma unroll
        for (int q = 0; q < 4; q++) o[nb][q] = 0.f;

    #pragma unroll
    for (int kb = 0; kb < 8; kb++) {
        const float* pb = &Pw[gID * 68 + kb * 8 + tig];
        const unsigned a0 = __float_as_uint(pb[0]);
        const unsigned a1 = __float_as_uint(pb[8 * 68]);
        const unsigned a2 = __float_as_uint(pb[4]);
        const unsigned a3 = __float_as_uint(pb[8 * 68 + 4]);
        #pragma unroll
        for (int nb = 0; nb < 4; nb++) {
            const float* vbp = &Vs[kb * 8 + tig][nb * 8 + gID];
            mma_tf32(o[nb][0], o[nb][1], o[nb][2], o[nb][3],
                     a0, a1, a2, a3,
                     __float_as_uint(vbp[0]), __float_as_uint(vbp[4 * 36]));
        }
    }

    if (r0 < WS2) {
        const int base = oRow[r0];
        #pragma unroll
        for (int nb = 0; nb < 4; nb++)
            *(float2*)&g_O[base + nb * 8 + 2 * tig] = make_float2(o[nb][0], o[nb][1]);
    }
    if (r1 < WS2) {
        const int base = oRow[r1];
        #pragma unroll
        for (int nb = 0; nb < 4; nb++)
            *(float2*)&g_O[base + nb * 8 + 2 * tig] = make_float2(o[nb][2], o[nb][3]);
    }
}

// ---------------------------------------------------------------------------
// K3: out = O @ w2^T + b2.  64-ROW tile (24KB smem), same staging map as K1.
// ---------------------------------------------------------------------------
__global__ __launch_bounds__(256) void k_proj(const float* __restrict__ b2,
                                              float* __restrict__ out) {
    __shared__ __align__(16) float Asl[6144];

    const int M0 = blockIdx.x * 64;
    const int t = threadIdx.x;
    const int lane = t & 31;
    const int w = t >> 5;
    const int mw = w >> 1;
    const int nw = w & 1;
    const int gID = lane >> 2;
    const int tig = lane & 3;

    const int rA = t >> 2, sub = t & 3;
    const int hi = sub & 1, jh = sub >> 1;
    const int gA = rA >> 4, rrA = rA & 15;
    const int slotA = (rrA >> 3) + 2 * hi;
    const int Lb = (rrA & 7) * 4;
    const int rot = (Lb + 8 * slotA) & 31;
    const int Fb = gA * 6 + jh * 3;

    #pragma unroll
    for (int chunk = 0; chunk < 2; chunk++) {
        const float* orow = &g_O[(M0 + rA) * 96 + chunk * 48 + 4 * hi + 24 * jh];
        unsigned sbase = (unsigned)__cvta_generic_to_shared(
            &Asl[chunk * 3072 + slotA * 768 + rot]);
        #pragma unroll
        for (int i = 0; i < 3; i++)
            cp_async16(sbase + (unsigned)((Fb + i) * 128), &orow[8 * i]);
    }
    asm volatile("cp.async.commit_group;");
    asm volatile("cp.async.wait_all;" ::: "memory");
    __syncthreads();

    const int rl0 = lane;
    const int rl1 = (lane + 8) & 31;
    const int rl2 = (lane + 16) & 31;
    const int rl3 = (lane + 24) & 31;

    const float2* WfB = (const float2*)g_W2f;

    float d[6][4];
    #pragma unroll
    for (int nb = 0; nb < 6; nb++)
        #pragma unroll
        for (int c = 0; c < 4; c++) d[nb][c] = 0.f;

    #pragma unroll
    for (int chunk = 0; chunk < 2; chunk++) {
        const float* Ab = &Asl[chunk * 3072];
        const float2* Wc = WfB + ((size_t)chunk) * 2304 + (nw * 6) * 32 + lane;
        #pragma unroll
        for (int ks = 0; ks < 6; ks++) {
            const int F0 = (mw * 6 + ks) * 32;
            const unsigned a0 = __float_as_uint(Ab[0 * 768 + F0 + rl0]);
            const unsigned a1 = __float_as_uint(Ab[1 * 768 + F0 + rl1]);
            const unsigned a2 = __float_as_uint(Ab[2 * 768 + F0 + rl2]);
            const unsigned a3 = __float_as_uint(Ab[3 * 768 + F0 + rl3]);
            float2 bf[6];
            #pragma unroll
            for (int nb = 0; nb < 6; nb++)
                bf[nb] = __ldg(&Wc[(ks * 12 + nb) * 32]);
            #pragma unroll
            for (int nb = 0; nb < 6; nb++)
                mma_tf32(d[nb][0], d[nb][1], d[nb][2], d[nb][3],
                         a0, a1, a2, a3,
                         __float_as_uint(bf[nb].x), __float_as_uint(bf[nb].y));
        }
    }

    #pragma unroll
    for (int h = 0; h < 2; h++) {
        const int row = M0 + mw * 16 + gID + 8 * h;
        #pragma unroll
        for (int nb = 0; nb < 6; nb++) {
            const int colp = nw * 48 + nb * 8 + tig * 2;
            float2 o;
            o.x = d[nb][h * 2 + 0] + __ldg(&b2[colp]);
            o.y = d[nb][h * 2 + 1] + __ldg(&b2[colp + 1]);
            *(float2*)&out[row * 96 + colp] = o;
        }
    }
}

// ---------------------------------------------------------------------------
extern "C" void kernel_launch(void* const* d_in, const int* in_sizes, int n_in,
                              void* d_out, int out_size) {
    const float* x  = (const float*)d_in[0];
    const float* w1 = (const float*)d_in[1];
    const float* b1 = (const float*)d_in[2];
    const float* w2 = (const float*)d_in[3];
    const float* b2 = (const float*)d_in[4];
    float* out = (float*)d_out;

    k_prep<<<144, 256>>>(w1, w2);
    k_qkv<<<SEQ * BATCH / 64, 256>>>(x, b1);
    k_attn<<<BATCH * HEADS * NWIN, 128>>>();
    k_proj<<<SEQ * BATCH / 64, 256>>>(b2, out);
}

// round 17
// speedup vs baseline: 2.1630x; 1.0924x over previous
#include <cuda_runtime.h>
#include <cuda_fp16.h>
#include <mma.h>
#include <math.h>

using namespace nvcuda;

#define BATCH 64
#define HW    56
#define SEQ   3136
#define EMB   96
#define HEADS 3
#define EH    32
#define WS    7
#define WS2   49
#define NWIN  64
#define N3E   288

#define SCALE 0.17677669529663687f  // 1/sqrt(32)

// Scratch (device globals)
__device__ __half g_QKV[BATCH * SEQ * N3E];  // fp16 dense [row][288]
// Pre-transposed tf32 weights in MMA fragment-major layout:
__device__ float g_W1f[3 * 2 * 6 * 12 * 32 * 2];
__device__ float g_W2f[2 * 6 * 12 * 32 * 2];

__device__ __forceinline__ void mma_tf32(float& d0, float& d1, float& d2, float& d3,
                                         unsigned a0, unsigned a1, unsigned a2, unsigned a3,
                                         unsigned b0, unsigned b1) {
    asm volatile(
        "mma.sync.aligned.m16n8k8.row.col.f32.tf32.tf32.f32 "
        "{%0,%1,%2,%3}, {%4,%5,%6,%7}, {%8,%9}, {%0,%1,%2,%3};\n"
        : "+f"(d0), "+f"(d1), "+f"(d2), "+f"(d3)
        : "r"(a0), "r"(a1), "r"(a2), "r"(a3), "r"(b0), "r"(b1));
}

__device__ __forceinline__ void cp_async16(unsigned saddr, const void* g) {
    asm volatile("cp.async.cg.shared.global [%0], [%1], 16;" :: "r"(saddr), "l"(g));
}

__device__ __forceinline__ unsigned h2f_u(__half h) {
    return __float_as_uint(__half2float(h));
}

// ---------------------------------------------------------------------------
// K0: pre-transpose w1/w2 into tf32 fragment-major layout (tiny).
// ---------------------------------------------------------------------------
__global__ __launch_bounds__(256) void k_prep(const float* __restrict__ w1,
                                              const float* __restrict__ w2) {
    int idx = blockIdx.x * 256 + threadIdx.x;
    if (idx < 27648) {
        const int r = idx & 1;
        const int lane = (idx >> 1) & 31;
        int rest = idx >> 6;
        const int nblk = rest % 12; rest /= 12;
        const int ks = rest % 6; rest /= 6;
        const int chunk = rest & 1;
        const int ct = rest >> 1;
        const int n = ct * 96 + nblk * 8 + (lane >> 2);
        const int k = chunk * 48 + ks * 8 + r * 4 + (lane & 3);
        g_W1f[idx] = wmma::__float_to_tf32(w1[n * 96 + k]);
    } else {
        int i2 = idx - 27648;
        if (i2 < 9216) {
            const int r = i2 & 1;
            const int lane = (i2 >> 1) & 31;
            int rest = i2 >> 6;
            const int nblk = rest % 12; rest /= 12;
            const int ks = rest % 6; rest /= 6;
            const int chunk = rest & 1;
            const int n = nblk * 8 + (lane >> 2);
            const int k = chunk * 48 + ks * 8 + r * 4 + (lane & 3);
            g_W2f[i2] = wmma::__float_to_tf32(w2[n * 96 + k]);
        }
    }
}

// ---------------------------------------------------------------------------
// K1: qkv = x @ w1^T + b1 via mma.sync tf32. 64-row tile, cp.async A staging,
// fragment-major B via LDG, fp16 output. (unchanged from R16)
// ---------------------------------------------------------------------------
__global__ __launch_bounds__(256) void k_qkv(const float* __restrict__ x,
                                             const float* __restrict__ b1) {
    __shared__ __align__(16) float Asl[6144];   // 24KB

    const int M0 = blockIdx.x * 64;
    const int t = threadIdx.x;
    const int lane = t & 31;
    const int w = t >> 5;
    const int mw = w >> 1;
    const int nw = w & 1;
    const int gID = lane >> 2;
    const int tig = lane & 3;

    const int rA = t >> 2, sub = t & 3;
    const int hi = sub & 1, jh = sub >> 1;
    const int gA = rA >> 4, rrA = rA & 15;
    const int slotA = (rrA >> 3) + 2 * hi;
    const int Lb = (rrA & 7) * 4;
    const int rot = (Lb + 8 * slotA) & 31;
    const int Fb = gA * 6 + jh * 3;

    #pragma unroll
    for (int chunk = 0; chunk < 2; chunk++) {
        const float* xrow = &x[(M0 + rA) * 96 + chunk * 48 + 4 * hi + 24 * jh];
        unsigned sbase = (unsigned)__cvta_generic_to_shared(
            &Asl[chunk * 3072 + slotA * 768 + rot]);
        #pragma unroll
        for (int i = 0; i < 3; i++)
            cp_async16(sbase + (unsigned)((Fb + i) * 128), &xrow[8 * i]);
    }
    asm volatile("cp.async.commit_group;");
    asm volatile("cp.async.wait_all;" ::: "memory");
    __syncthreads();

    const int rl0 = lane;
    const int rl1 = (lane + 8) & 31;
    const int rl2 = (lane + 16) & 31;
    const int rl3 = (lane + 24) & 31;

    const float2* WfB = (const float2*)g_W1f;

    for (int ct = 0; ct < 3; ct++) {
        float d[6][4];
        #pragma unroll
        for (int nb = 0; nb < 6; nb++)
            #pragma unroll
            for (int c = 0; c < 4; c++) d[nb][c] = 0.f;

        #pragma unroll
        for (int chunk = 0; chunk < 2; chunk++) {
            const float* Ab = &Asl[chunk * 3072];
            const float2* Wc = WfB + ((size_t)(ct * 2 + chunk)) * 2304 + (nw * 6) * 32 + lane;
            #pragma unroll
            for (int ks = 0; ks < 6; ks++) {
                const int F0 = (mw * 6 + ks) * 32;
                const unsigned a0 = __float_as_uint(Ab[0 * 768 + F0 + rl0]);
                const unsigned a1 = __float_as_uint(Ab[1 * 768 + F0 + rl1]);
                const unsigned a2 = __float_as_uint(Ab[2 * 768 + F0 + rl2]);
                const unsigned a3 = __float_as_uint(Ab[3 * 768 + F0 + rl3]);
                float2 bf[6];
                #pragma unroll
                for (int nb = 0; nb < 6; nb++)
                    bf[nb] = __ldg(&Wc[(ks * 12 + nb) * 32]);
                #pragma unroll
                for (int nb = 0; nb < 6; nb++)
                    mma_tf32(d[nb][0], d[nb][1], d[nb][2], d[nb][3],
                             a0, a1, a2, a3,
                             __float_as_uint(bf[nb].x), __float_as_uint(bf[nb].y));
            }
        }

        const int c0 = ct * 96;
        #pragma unroll
        for (int h = 0; h < 2; h++) {
            const int row = M0 + mw * 16 + gID + 8 * h;
            #pragma unroll
            for (int nb = 0; nb < 6; nb++) {
                const int colp = nw * 48 + nb * 8 + tig * 2;
                const float ox = d[nb][h * 2 + 0] + __ldg(&b1[c0 + colp]);
                const float oy = d[nb][h * 2 + 1] + __ldg(&b1[c0 + colp + 1]);
                *(__half2*)&g_QKV[row * N3E + c0 + colp] = __floats2half2_rn(ox, oy);
            }
        }
    }
}

// ---------------------------------------------------------------------------
// K2 (FUSED attention + out-projection). One block per (b, window),
// 384 threads = 12 warps = 3 heads x 4 row-blocks.
// - Q/K/V staged fp16 (pure copy from g_QKV); SCALE applied to S accums.
// - S/softmax in registers (as R13+); P staged fp16, overlays dead Q+K.
// - O staged fp32 [64][100] (overlays P); proj GEMM: A=Os (raw fp32 ->
//   HW tf32 truncation), B=g_W2f fragments; epilogue: inverse-rolled rows,
//   dense 96-col write with bias. No g_O, no k_proj.
// ---------------------------------------------------------------------------
__global__ __launch_bounds__(384) void k_attn_proj(const float* __restrict__ b2,
                                                   float* __restrict__ out) {
    __shared__ __align__(16) char smraw[41472];
    __shared__ int sRowT[WS2];
    __shared__ int oRowT[WS2];
    __half* smH = (__half*)smraw;
    __half* sQ = smH;            // [3][64][36]
    __half* sK = smH + 6912;
    __half* sV = smH + 13824;
    float*  Os = (float*)smraw;  // [64][100] overlay (after PV)

    const int blk = blockIdx.x;
    const int win = blk & 63;
    const int b = blk >> 6;
    const int t = threadIdx.x;
    const int w = t >> 5, lane = t & 31;
    const int gID = lane >> 2, tig = lane & 3;
    const int h = w >> 2;        // head 0..2
    const int mw = w & 3;        // row-block 0..3
    const int m0 = mw * 16;
    const int wh = win >> 3, ww = win & 7;

    if (t < WS2) {
        const int m1 = t / 7, m2 = t % 7;
        {
            const int y  = (wh * WS + m1 + 4) % HW;
            const int xx = (ww * WS + m2 + 4) % HW;
            sRowT[t] = (b * SEQ + y * HW + xx) * N3E;
        }
        {
            const int y  = (wh * WS + m1 + 3) % HW;
            const int xx = (ww * WS + m2 + 3) % HW;
            oRowT[t] = (b * SEQ + y * HW + xx) * EMB;
        }
    }
    __syncthreads();

    // Stage Q/K/V fp16 for all 3 heads (pure copy, zero-pad rows 49..63)
    for (int i = t; i < 3 * 64 * EH; i += 384) {
        const int hh = i >> 11;          // /2048
        const int rem = i & 2047;
        const int m = rem >> 5, k = rem & 31;
        __half q = __float2half(0.f), kk = q, vv = q;
        if (m < WS2) {
            const int a = sRowT[m] + hh * 96 + k * 3;
            q  = g_QKV[a];
            kk = g_QKV[a + 1];
            vv = g_QKV[a + 2];
        }
        const int di = (hh * 64 + m) * 36 + k;
        sQ[di] = q; sK[di] = kk; sV[di] = vv;
    }
    __syncthreads();

    // ---- S = Q @ K^T (head h, rows m0..m0+15) ----
    float c[8][4];
    #pragma unroll
    for (int nb = 0; nb < 8; nb++)
        #pragma unroll
        for (int q = 0; q < 4; q++) c[nb][q] = 0.f;

    const int hbase = h * 64;
    #pragma unroll
    for (int ks = 0; ks < 4; ks++) {
        const __half* qb = &sQ[(hbase + m0 + gID) * 36 + ks * 8 + tig];
        const unsigned a0 = h2f_u(qb[0]);
        const unsigned a1 = h2f_u(qb[8 * 36]);
        const unsigned a2 = h2f_u(qb[4]);
        const unsigned a3 = h2f_u(qb[8 * 36 + 4]);
        #pragma unroll
        for (int nb = 0; nb < 8; nb++) {
            const __half* kbp = &sK[(hbase + nb * 8 + gID) * 36 + ks * 8 + tig];
            mma_tf32(c[nb][0], c[nb][1], c[nb][2], c[nb][3],
                     a0, a1, a2, a3, h2f_u(kbp[0]), h2f_u(kbp[4]));
        }
    }

    // ---- scale + masks + softmax in registers ----
    const bool lastRow = (wh == 7);
    const bool lastCol = (ww == 7);
    const int r0 = m0 + gID;
    const int r1 = r0 + 8;
    const bool rD0 = (r0 >= 28), rM0 = (r0 % 7) >= 4;
    const bool rD1 = (r1 >= 28), rM1 = (r1 % 7) >= 4;

    float mx0 = -1e30f, mx1 = -1e30f;
    #pragma unroll
    for (int nb = 0; nb < 8; nb++) {
        #pragma unroll
        for (int bc = 0; bc < 2; bc++) {
            const int col = nb * 8 + 2 * tig + bc;
            const bool cOK = (col < WS2);
            const bool cD = (col >= 28);
            const bool cM = (col % 7) >= 4;
            const bool bad0 = !cOK || (lastRow && (rD0 != cD)) || (lastCol && (rM0 != cM));
            const bool bad1 = !cOK || (lastRow && (rD1 != cD)) || (lastCol && (rM1 != cM));
            c[nb][bc]     = bad0 ? -1e30f : c[nb][bc] * SCALE;
            c[nb][2 + bc] = bad1 ? -1e30f : c[nb][2 + bc] * SCALE;
            mx0 = fmaxf(mx0, c[nb][bc]);
            mx1 = fmaxf(mx1, c[nb][2 + bc]);
        }
    }
    mx0 = fmaxf(mx0, __shfl_xor_sync(0xffffffff, mx0, 1));
    mx0 = fmaxf(mx0, __shfl_xor_sync(0xffffffff, mx0, 2));
    mx1 = fmaxf(mx1, __shfl_xor_sync(0xffffffff, mx1, 1));
    mx1 = fmaxf(mx1, __shfl_xor_sync(0xffffffff, mx1, 2));

    float s0 = 0.f, s1 = 0.f;
    #pragma unroll
    for (int nb = 0; nb < 8; nb++) {
        #pragma unroll
        for (int bc = 0; bc < 2; bc++) {
            c[nb][bc]     = __expf(c[nb][bc] - mx0);     s0 += c[nb][bc];
            c[nb][2 + bc] = __expf(c[nb][2 + bc] - mx1); s1 += c[nb][2 + bc];
        }
    }
    s0 += __shfl_xor_sync(0xffffffff, s0, 1);
    s0 += __shfl_xor_sync(0xffffffff, s0, 2);
    s1 += __shfl_xor_sync(0xffffffff, s1, 1);
    s1 += __shfl_xor_sync(0xffffffff, s1, 2);
    const float inv0 = __frcp_rn(s0);
    const float inv1 = __frcp_rn(s1);

    // All warps past S (done reading Q/K) before P overlays them
    __syncthreads();

    // ---- stage P fp16 per-warp: 16 x 72 halves (overlays Q+K exactly) ----
    __half* Pw = smH + w * 1152;
    #pragma unroll
    for (int nb = 0; nb < 8; nb++) {
        *(__half2*)&Pw[gID * 72 + nb * 8 + 2 * tig] =
            __floats2half2_rn(c[nb][0] * inv0, c[nb][1] * inv0);
        *(__half2*)&Pw[(gID + 8) * 72 + nb * 8 + 2 * tig] =
            __floats2half2_rn(c[nb][2] * inv1, c[nb][3] * inv1);
    }
    __syncwarp();

    // ---- O = P @ V (head h): 4 n-blocks of 8 cols ----
    float o[4][4];
    #pragma unroll
    for (int nb = 0; nb < 4; nb++)
        #pragma unroll
        for (int q = 0; q < 4; q++) o[nb][q] = 0.f;

    #pragma unroll
    for (int kb = 0; kb < 8; kb++) {
        const __half* pb = &Pw[gID * 72 + kb * 8 + tig];
        const unsigned a0 = h2f_u(pb[0]);
        const unsigned a1 = h2f_u(pb[8 * 72]);
        const unsigned a2 = h2f_u(pb[4]);
        const unsigned a3 = h2f_u(pb[8 * 72 + 4]);
        #pragma unroll
        for (int nb = 0; nb < 4; nb++) {
            const __half* vbp = &sV[(hbase + kb * 8 + tig) * 36 + nb * 8 + gID];
            mma_tf32(o[nb][0], o[nb][1], o[nb][2], o[nb][3],
                     a0, a1, a2, a3, h2f_u(vbp[0]), h2f_u(vbp[4 * 36]));
        }
    }

    // All warps done with P/V reads before Os overlays the smem base
    __syncthreads();

    // ---- stage O fp32: Os[64][100], cols h*32 + nb*8 + 2tig ----
    #pragma unroll
    for (int nb = 0; nb < 4; nb++) {
        *(float2*)&Os[(m0 + gID) * 100 + h * 32 + nb * 8 + 2 * tig] =
            make_float2(o[nb][0], o[nb][1]);
        *(float2*)&Os[(m0 + gID + 8) * 100 + h * 32 + nb * 8 + 2 * tig] =
            make_float2(o[nb][2], o[nb][3]);
    }
    __syncthreads();

    // ---- out-projection: out[49,96] = Os[*,96] @ w2^T + b2 ----
    // Warp: mw2 = w&3 -> 16 rows; nw2 = w>>2 -> 32 cols (4 nblk).
    const int mw2 = w & 3;
    const int nw2 = w >> 2;
    const float2* WfB = (const float2*)g_W2f;

    float d[4][4];
    #pragma unroll
    for (int nb = 0; nb < 4; nb++)
        #pragma unroll
        for (int q = 0; q < 4; q++) d[nb][q] = 0.f;

    #pragma unroll
    for (int ks = 0; ks < 12; ks++) {
        const int chunk = ks / 6, ksl = ks % 6;
        const float* ab = &Os[(mw2 * 16 + gID) * 100 + ks * 8 + tig];
        const unsigned a0 = __float_as_uint(ab[0]);
        const unsigned a1 = __float_as_uint(ab[8 * 100]);
        const unsigned a2 = __float_as_uint(ab[4]);
        const unsigned a3 = __float_as_uint(ab[8 * 100 + 4]);
        const float2* Wc = WfB + (size_t)chunk * 2304 + (ksl * 12 + nw2 * 4) * 32 + lane;
        float2 bf[4];
        #pragma unroll
        for (int nb = 0; nb < 4; nb++) bf[nb] = __ldg(&Wc[nb * 32]);
        #pragma unroll
        for (int nb = 0; nb < 4; nb++)
            mma_tf32(d[nb][0], d[nb][1], d[nb][2], d[nb][3],
                     a0, a1, a2, a3,
                     __float_as_uint(bf[nb].x), __float_as_uint(bf[nb].y));
    }

    // Epilogue: inverse-rolled rows, bias, float2 stores
    const int pr0 = mw2 * 16 + gID;
    const int pr1 = pr0 + 8;
    if (pr0 < WS2) {
        const int base = oRowT[pr0];
        #pragma unroll
        for (int nb = 0; nb < 4; nb++) {
            const int col = nw2 * 32 + nb * 8 + 2 * tig;
            float2 ov;
            ov.x = d[nb][0] + __ldg(&b2[col]);
            ov.y = d[nb][1] + __ldg(&b2[col + 1]);
            *(float2*)&out[base + col] = ov;
        }
    }
    if (pr1 < WS2) {
        const int base = oRowT[pr1];
        #pragma unroll
        for (int nb = 0; nb < 4; nb++) {
            const int col = nw2 * 32 + nb * 8 + 2 * tig;
            float2 ov;
            ov.x = d[nb][2] + __ldg(&b2[col]);
            ov.y = d[nb][3] + __ldg(&b2[col + 1]);
            *(float2*)&out[base + col] = ov;
        }
    }
}

// ---------------------------------------------------------------------------
extern "C" void kernel_launch(void* const* d_in, const int* in_sizes, int n_in,
                              void* d_out, int out_size) {
    const float* x  = (const float*)d_in[0];
    const float* w1 = (const float*)d_in[1];
    const float* b1 = (const float*)d_in[2];
    const float* w2 = (const float*)d_in[3];
    const float* b2 = (const float*)d_in[4];
    float* out = (float*)d_out;

    k_prep<<<144, 256>>>(w1, w2);
    k_qkv<<<SEQ * BATCH / 64, 256>>>(x, b1);
    k_attn_proj<<<BATCH * NWIN, 384>>>(b2, out);
}